// round 9
// baseline (speedup 1.0000x reference)
#include <cuda_runtime.h>
#include <cstdint>

#define NB 8
#define SEQ 2048
#define DIN 512
#define DH 128
#define MTOT (NB*SEQ)

#define ASTR 36    // proj A smem row stride
#define BSTR 136   // proj B smem row stride

// Scratch (device globals: allocation-free rule)
__device__ float g_q[MTOT*DH];
__device__ float g_k[MTOT*DH];
__device__ float g_v[MTOT*DH];

// ---------------------------------------------------------------------------
// helpers (baseline sm_80 ISA)
// ---------------------------------------------------------------------------
__device__ __forceinline__ uint32_t f2tf(float x) {
    uint32_t u;
    asm("cvt.rna.tf32.f32 %0, %1;" : "=r"(u) : "f"(x));
    return u;
}
__device__ __forceinline__ void mma8(float* c, const uint32_t* a, const uint32_t* b) {
    asm volatile(
        "mma.sync.aligned.m16n8k8.row.col.f32.tf32.tf32.f32 "
        "{%0,%1,%2,%3}, {%4,%5,%6,%7}, {%8,%9}, {%0,%1,%2,%3};"
        : "+f"(c[0]), "+f"(c[1]), "+f"(c[2]), "+f"(c[3])
        : "r"(a[0]), "r"(a[1]), "r"(a[2]), "r"(a[3]), "r"(b[0]), "r"(b[1]));
}
__device__ __forceinline__ int bswz(int k, int n) {
    return n ^ (((k >> 2) & 7) << 2);
}
__device__ __forceinline__ void cp16(void* dst, const void* src) {
    uint32_t d;
    asm("{ .reg .u64 t; cvta.to.shared.u64 t, %1; cvt.u32.u64 %0, t; }" : "=r"(d) : "l"(dst));
    asm volatile("cp.async.cg.shared.global [%0], [%1], 16;" :: "r"(d), "l"(src));
}
#define CP_COMMIT() asm volatile("cp.async.commit_group;" ::: "memory")
#define CP_WAIT1()  asm volatile("cp.async.wait_group 1;" ::: "memory")
#define CP_WAIT0()  asm volatile("cp.async.wait_group 0;" ::: "memory")

// proj BK=32 stage, BM=128/BN=128: 8 warps 4(m) x 2(n).
__device__ __forceinline__ void mma_stage(const uint32_t* As, const uint32_t* Bs,
                                          int wm, int wn, int lane,
                                          float acc[2][8][4])
{
    int g = lane >> 2, t = lane & 3;
    #pragma unroll
    for (int s = 0; s < 4; s++) {
        int k8 = s * 8;
        uint32_t a[2][4], b[8][2];
        #pragma unroll
        for (int mt = 0; mt < 2; mt++) {
            int r = wm * 32 + mt * 16 + g;
            a[mt][0] = As[r * ASTR + k8 + t];
            a[mt][1] = As[(r + 8) * ASTR + k8 + t];
            a[mt][2] = As[r * ASTR + k8 + t + 4];
            a[mt][3] = As[(r + 8) * ASTR + k8 + t + 4];
        }
        #pragma unroll
        for (int nt = 0; nt < 8; nt++) {
            int c = wn * 64 + nt * 8 + g;
            b[nt][0] = Bs[(k8 + t) * BSTR + bswz(k8 + t, c)];
            b[nt][1] = Bs[(k8 + t + 4) * BSTR + bswz(k8 + t + 4, c)];
        }
        #pragma unroll
        for (int mt = 0; mt < 2; mt++)
            #pragma unroll
            for (int nt = 0; nt < 8; nt++)
                mma8(acc[mt][nt], a[mt], b[nt]);
    }
}

// ===========================================================================
// Fused QKV projection via tf32 MMA (unchanged)
// ===========================================================================
__global__ __launch_bounds__(256, 2) void proj_kernel(
    const float* __restrict__ x0, const float* __restrict__ x1, const float* __restrict__ x2,
    const float* __restrict__ w0, const float* __restrict__ w1, const float* __restrict__ w2,
    const float* __restrict__ b0, const float* __restrict__ b1, const float* __restrict__ b2)
{
    __shared__ uint32_t As[128 * ASTR];
    __shared__ uint32_t Bs[32 * BSTR];

    int sel = blockIdx.y;
    const float* X    = sel == 0 ? x0 : (sel == 1 ? x1 : x2);
    const float* W    = sel == 0 ? w0 : (sel == 1 ? w1 : w2);
    const float* bias = sel == 0 ? b0 : (sel == 1 ? b1 : b2);
    float*       Out  = sel == 0 ? g_q : (sel == 1 ? g_k : g_v);

    int m0  = blockIdx.x * 128;
    int tid = threadIdx.x;
    int lane = tid & 31, wid = tid >> 5;
    int wm = wid & 3, wn = wid >> 2;

    float acc[2][8][4];
    #pragma unroll
    for (int i = 0; i < 2; i++)
        #pragma unroll
        for (int j = 0; j < 8; j++)
            #pragma unroll
            for (int q = 0; q < 4; q++) acc[i][j][q] = 0.f;

    for (int k0 = 0; k0 < DIN; k0 += 32) {
        #pragma unroll
        for (int it = 0; it < 4; it++) {
            int idx = tid + it * 256;
            int r = idx >> 3, c4 = idx & 7;
            float4 v = *(const float4*)(X + (size_t)(m0 + r) * DIN + k0 + c4 * 4);
            uint4 u = { f2tf(v.x), f2tf(v.y), f2tf(v.z), f2tf(v.w) };
            *(uint4*)&As[r * ASTR + c4 * 4] = u;
        }
        #pragma unroll
        for (int it = 0; it < 4; it++) {
            int idx = tid + it * 256;
            int r = idx >> 5, c4 = idx & 31;
            float4 v = *(const float4*)(W + (size_t)(k0 + r) * DH + c4 * 4);
            uint4 u = { f2tf(v.x), f2tf(v.y), f2tf(v.z), f2tf(v.w) };
            *(uint4*)&Bs[r * BSTR + bswz(r, c4 * 4)] = u;
        }
        __syncthreads();
        mma_stage(As, Bs, wm, wn, lane, acc);
        __syncthreads();
    }

    int g = lane >> 2, t = lane & 3;
    #pragma unroll
    for (int mt = 0; mt < 2; mt++) {
        int row = m0 + wm * 32 + mt * 16 + g;
        #pragma unroll
        for (int nt = 0; nt < 8; nt++) {
            int col = wn * 64 + nt * 8 + 2 * t;
            float bb0 = bias[col], bb1 = bias[col + 1];
            uint2 lo = { f2tf(acc[mt][nt][0] + bb0), f2tf(acc[mt][nt][1] + bb1) };
            uint2 hi = { f2tf(acc[mt][nt][2] + bb0), f2tf(acc[mt][nt][3] + bb1) };
            *(uint2*)(Out + (size_t)row * DH + col)       = lo;
            *(uint2*)(Out + (size_t)(row + 8) * DH + col) = hi;
        }
    }
}

// ===========================================================================
// Fused flash attention: per block 64 q-rows, stream keys in tiles of 32.
// 8 warps as 2(m) x 4(n). Online softmax, P via smem, O accumulated in regs.
// Smem (u32 words):
//   Qs 0..8192      64x128, swz col^((r&7)<<2)
//   K0 8192, K1 12288   32x128 each, same swz
//   V0 16384, V1 20480  32x128 each, swz col^((r&3)<<3)
//   Ps 24576..26880     64x36 (P tile, K-major, A-operand layout)
//   redm 26880 (4x64), reds 27136 (4x64)
// total 27392 words = 109568 B -> 2 blocks/SM
// ===========================================================================
#define FL_SMEM (27392 * 4)
#define TN 32

__global__ __launch_bounds__(256, 2) void flash_kernel(float* __restrict__ Out)
{
    extern __shared__ uint32_t ds[];
    uint32_t* Qs = ds;
    uint32_t* Kbuf[2] = { ds + 8192,  ds + 12288 };
    uint32_t* Vbuf[2] = { ds + 16384, ds + 20480 };
    uint32_t* Ps = ds + 24576;
    float* redm = (float*)(ds + 26880);
    float* reds = (float*)(ds + 27136);

    int b  = blockIdx.y;
    int m0 = blockIdx.x * 64;
    const float* Qg = g_q + (size_t)b * SEQ * DH + (size_t)m0 * DH;
    const float* Kg = g_k + (size_t)b * SEQ * DH;
    const float* Vg = g_v + (size_t)b * SEQ * DH;
    float*       Ob = Out + (size_t)b * SEQ * DH + (size_t)m0 * DH;

    int tid = threadIdx.x, lane = tid & 31, wid = tid >> 5;
    int g = lane >> 2, t = lane & 3;
    int wm = wid & 1, wn = wid >> 1;
    int swq = g << 2;          // Q/K frag col swizzle
    int swv = t << 3;          // V frag col swizzle

    // ---- prologue loads: Q (resident) + K0/V0 ----
    #pragma unroll
    for (int it = 0; it < 8; it++) {
        int idx = tid + it * 256;
        int r = idx >> 5, c4 = idx & 31;
        cp16(&Qs[r * 128 + ((c4 * 4) ^ ((r & 7) << 2))], Qg + (size_t)r * DH + c4 * 4);
    }
    #pragma unroll
    for (int it = 0; it < 4; it++) {
        int idx = tid + it * 256;
        int r = idx >> 5, c4 = idx & 31;
        cp16(&Kbuf[0][r * 128 + ((c4 * 4) ^ ((r & 7) << 2))], Kg + (size_t)r * DH + c4 * 4);
        cp16(&Vbuf[0][r * 128 + ((c4 * 4) ^ ((r & 3) << 3))], Vg + (size_t)r * DH + c4 * 4);
    }
    CP_COMMIT();

    float m_run[2][2], l_run[2][2];
    #pragma unroll
    for (int i = 0; i < 2; i++)
        #pragma unroll
        for (int h = 0; h < 2; h++) { m_run[i][h] = -1e30f; l_run[i][h] = 0.f; }

    float o[2][4][4];
    #pragma unroll
    for (int i = 0; i < 2; i++)
        #pragma unroll
        for (int j = 0; j < 4; j++)
            #pragma unroll
            for (int q = 0; q < 4; q++) o[i][j][q] = 0.f;

    const float scaleQK = 0.08838834764831845f;  // 1/sqrt(128)
    int ra = wm * 32 + g;   // base row (mt=0); mt=1 adds 16

    for (int i = 0; i < SEQ / TN; i++) {
        int cur = i & 1;
        if (i < SEQ / TN - 1) {
            int k1 = (i + 1) * TN;
            uint32_t* Kn = Kbuf[cur ^ 1];
            uint32_t* Vn = Vbuf[cur ^ 1];
            #pragma unroll
            for (int it = 0; it < 4; it++) {
                int idx = tid + it * 256;
                int r = idx >> 5, c4 = idx & 31;
                cp16(&Kn[r * 128 + ((c4 * 4) ^ ((r & 7) << 2))], Kg + (size_t)(k1 + r) * DH + c4 * 4);
                cp16(&Vn[r * 128 + ((c4 * 4) ^ ((r & 3) << 3))], Vg + (size_t)(k1 + r) * DH + c4 * 4);
            }
            CP_COMMIT();
            CP_WAIT1();
        } else {
            CP_WAIT0();
        }
        __syncthreads();   // X: K/V cur ready; prev iter's P/red traffic drained

        const uint32_t* Kc = Kbuf[cur];
        const uint32_t* Vc = Vbuf[cur];

        // ---- S = Q . K^T  (64x32 tile; warp covers rows wm*32..+31, cols wn*8..+7)
        float s_[2][4];
        #pragma unroll
        for (int mt = 0; mt < 2; mt++)
            #pragma unroll
            for (int q = 0; q < 4; q++) s_[mt][q] = 0.f;

        {
            int c = wn * 8 + g;
            #pragma unroll
            for (int ks = 0; ks < 16; ks++) {
                int k8 = ks * 8;
                uint32_t a0[4], a1[4], bb[2];
                a0[0] = Qs[ra * 128 + ((k8 + t) ^ swq)];
                a0[1] = Qs[(ra + 8) * 128 + ((k8 + t) ^ swq)];
                a0[2] = Qs[ra * 128 + ((k8 + t + 4) ^ swq)];
                a0[3] = Qs[(ra + 8) * 128 + ((k8 + t + 4) ^ swq)];
                a1[0] = Qs[(ra + 16) * 128 + ((k8 + t) ^ swq)];
                a1[1] = Qs[(ra + 24) * 128 + ((k8 + t) ^ swq)];
                a1[2] = Qs[(ra + 16) * 128 + ((k8 + t + 4) ^ swq)];
                a1[3] = Qs[(ra + 24) * 128 + ((k8 + t + 4) ^ swq)];
                bb[0] = Kc[c * 128 + ((k8 + t) ^ swq)];
                bb[1] = Kc[c * 128 + ((k8 + t + 4) ^ swq)];
                mma8(s_[0], a0, bb);
                mma8(s_[1], a1, bb);
            }
        }
        #pragma unroll
        for (int mt = 0; mt < 2; mt++)
            #pragma unroll
            for (int q = 0; q < 4; q++) s_[mt][q] *= scaleQK;

        // ---- per-row tile max (warp-slice, then cross-warp via redm)
        #pragma unroll
        for (int mt = 0; mt < 2; mt++) {
            float p0 = fmaxf(s_[mt][0], s_[mt][1]);   // row ra+mt*16
            float p1 = fmaxf(s_[mt][2], s_[mt][3]);   // row ra+mt*16+8
            p0 = fmaxf(p0, __shfl_xor_sync(0xffffffffu, p0, 1));
            p0 = fmaxf(p0, __shfl_xor_sync(0xffffffffu, p0, 2));
            p1 = fmaxf(p1, __shfl_xor_sync(0xffffffffu, p1, 1));
            p1 = fmaxf(p1, __shfl_xor_sync(0xffffffffu, p1, 2));
            if (t == 0) {
                redm[wn * 64 + wm * 32 + mt * 16 + g]     = p0;
                redm[wn * 64 + wm * 32 + mt * 16 + g + 8] = p1;
            }
        }
        __syncthreads();   // Y

        float sc[2][2];
        #pragma unroll
        for (int mt = 0; mt < 2; mt++)
            #pragma unroll
            for (int h = 0; h < 2; h++) {
                int r = wm * 32 + mt * 16 + h * 8 + g;
                float tm = fmaxf(fmaxf(redm[r], redm[64 + r]),
                                 fmaxf(redm[128 + r], redm[192 + r]));
                float mn = fmaxf(m_run[mt][h], tm);
                sc[mt][h] = __expf(m_run[mt][h] - mn);
                m_run[mt][h] = mn;
            }

        // ---- P = exp(s - m), store to Ps; partial row sums -> reds
        #pragma unroll
        for (int mt = 0; mt < 2; mt++) {
            float e0 = __expf(s_[mt][0] - m_run[mt][0]);
            float e1 = __expf(s_[mt][1] - m_run[mt][0]);
            float e2 = __expf(s_[mt][2] - m_run[mt][1]);
            float e3 = __expf(s_[mt][3] - m_run[mt][1]);
            int r = wm * 32 + mt * 16 + g;
            uint2 u0 = { f2tf(e0), f2tf(e1) };
            uint2 u1 = { f2tf(e2), f2tf(e3) };
            *(uint2*)&Ps[r * 36 + wn * 8 + 2 * t]       = u0;
            *(uint2*)&Ps[(r + 8) * 36 + wn * 8 + 2 * t] = u1;
            float q0 = e0 + e1, q1 = e2 + e3;
            q0 += __shfl_xor_sync(0xffffffffu, q0, 1);
            q0 += __shfl_xor_sync(0xffffffffu, q0, 2);
            q1 += __shfl_xor_sync(0xffffffffu, q1, 1);
            q1 += __shfl_xor_sync(0xffffffffu, q1, 2);
            if (t == 0) {
                reds[wn * 64 + r]     = q0;
                reds[wn * 64 + r + 8] = q1;
            }
        }

        // ---- rescale O by sc while stores land
        #pragma unroll
        for (int mt = 0; mt < 2; mt++)
            #pragma unroll
            for (int nt = 0; nt < 4; nt++) {
                o[mt][nt][0] *= sc[mt][0];
                o[mt][nt][1] *= sc[mt][0];
                o[mt][nt][2] *= sc[mt][1];
                o[mt][nt][3] *= sc[mt][1];
            }
        __syncthreads();   // Z: P + reds visible

        // ---- l update
        #pragma unroll
        for (int mt = 0; mt < 2; mt++)
            #pragma unroll
            for (int h = 0; h < 2; h++) {
                int r = wm * 32 + mt * 16 + h * 8 + g;
                float ts = reds[r] + reds[64 + r] + reds[128 + r] + reds[192 + r];
                l_run[mt][h] = l_run[mt][h] * sc[mt][h] + ts;
            }

        // ---- O += P . V   (warp covers rows wm*32..+31, dh cols wn*32..+31)
        #pragma unroll
        for (int ks = 0; ks < 4; ks++) {
            int k8 = ks * 8;
            uint32_t a0[4], a1[4], bb[4][2];
            a0[0] = Ps[ra * 36 + k8 + t];
            a0[1] = Ps[(ra + 8) * 36 + k8 + t];
            a0[2] = Ps[ra * 36 + k8 + t + 4];
            a0[3] = Ps[(ra + 8) * 36 + k8 + t + 4];
            a1[0] = Ps[(ra + 16) * 36 + k8 + t];
            a1[1] = Ps[(ra + 24) * 36 + k8 + t];
            a1[2] = Ps[(ra + 16) * 36 + k8 + t + 4];
            a1[3] = Ps[(ra + 24) * 36 + k8 + t + 4];
            #pragma unroll
            for (int nt = 0; nt < 4; nt++) {
                int c = wn * 32 + nt * 8 + g;
                bb[nt][0] = Vc[(k8 + t) * 128 + (c ^ swv)];
                bb[nt][1] = Vc[(k8 + t + 4) * 128 + (c ^ swv)];
            }
            #pragma unroll
            for (int nt = 0; nt < 4; nt++) {
                mma8(o[0][nt], a0, bb[nt]);
                mma8(o[1][nt], a1, bb[nt]);
            }
        }
    }

    // ---- epilogue: O / l -> gmem
    float inv[2][2];
    #pragma unroll
    for (int mt = 0; mt < 2; mt++)
        #pragma unroll
        for (int h = 0; h < 2; h++) inv[mt][h] = 1.0f / l_run[mt][h];

    #pragma unroll
    for (int mt = 0; mt < 2; mt++) {
        int row = wm * 32 + mt * 16 + g;
        #pragma unroll
        for (int nt = 0; nt < 4; nt++) {
            int col = wn * 32 + nt * 8 + 2 * t;
            float2 lo = { o[mt][nt][0] * inv[mt][0], o[mt][nt][1] * inv[mt][0] };
            float2 hi = { o[mt][nt][2] * inv[mt][1], o[mt][nt][3] * inv[mt][1] };
            *(float2*)(Ob + (size_t)row * DH + col)       = lo;
            *(float2*)(Ob + (size_t)(row + 8) * DH + col) = hi;
        }
    }
}

// ===========================================================================
extern "C" void kernel_launch(void* const* d_in, const int* in_sizes, int n_in,
                              void* d_out, int out_size)
{
    const float* q_in = (const float*)d_in[0];
    const float* k_in = (const float*)d_in[1];
    const float* v_in = (const float*)d_in[2];
    const float* Wq   = (const float*)d_in[3];
    const float* Wk   = (const float*)d_in[4];
    const float* Wv   = (const float*)d_in[5];
    const float* bq   = (const float*)d_in[6];
    const float* bk   = (const float*)d_in[7];
    const float* bv   = (const float*)d_in[8];
    float* out        = (float*)d_out;

    static bool attr_done = false;
    if (!attr_done) {
        cudaFuncSetAttribute(flash_kernel, cudaFuncAttributeMaxDynamicSharedMemorySize, FL_SMEM);
        attr_done = true;
    }

    proj_kernel<<<dim3(MTOT / 128, 3), 256>>>(q_in, k_in, v_in, Wq, Wk, Wv, bq, bk, bv);
    flash_kernel<<<dim3(SEQ / 64, NB), 256, FL_SMEM>>>(out);
}

// round 10
// speedup vs baseline: 1.1060x; 1.1060x over previous
#include <cuda_runtime.h>
#include <cstdint>

#define NB 8
#define SEQ 2048
#define DIN 512
#define DH 128
#define MTOT (NB*SEQ)

#define ASTR 36    // proj A smem row stride
#define BSTR 136   // proj B smem row stride

// Scratch (device globals: allocation-free rule)
__device__ float g_q[MTOT*DH];
__device__ float g_k[MTOT*DH];
__device__ float g_v[MTOT*DH];   // TRANSPOSED: [b][dh][seq]

// ---------------------------------------------------------------------------
// helpers (baseline sm_75/sm_80 ISA only)
// ---------------------------------------------------------------------------
__device__ __forceinline__ uint32_t smem_u32(const void* p) {
    uint32_t a;
    asm("{ .reg .u64 t; cvta.to.shared.u64 t, %1; cvt.u32.u64 %0, t; }" : "=r"(a) : "l"(p));
    return a;
}
__device__ __forceinline__ uint32_t f2tf(float x) {
    uint32_t u;
    asm("cvt.rna.tf32.f32 %0, %1;" : "=r"(u) : "f"(x));
    return u;
}
__device__ __forceinline__ void mma8(float* c, const uint32_t* a, const uint32_t* b) {
    asm volatile(
        "mma.sync.aligned.m16n8k8.row.col.f32.tf32.tf32.f32 "
        "{%0,%1,%2,%3}, {%4,%5,%6,%7}, {%8,%9}, {%0,%1,%2,%3};"
        : "+f"(c[0]), "+f"(c[1]), "+f"(c[2]), "+f"(c[3])
        : "r"(a[0]), "r"(a[1]), "r"(a[2]), "r"(a[3]), "r"(b[0]), "r"(b[1]));
}
__device__ __forceinline__ void ldsm4(uint32_t* r, uint32_t addr) {
    asm volatile("ldmatrix.sync.aligned.m8n8.x4.shared.b16 {%0,%1,%2,%3}, [%4];"
        : "=r"(r[0]), "=r"(r[1]), "=r"(r[2]), "=r"(r[3]) : "r"(addr));
}
__device__ __forceinline__ void ldsm2(uint32_t* r, uint32_t addr) {
    asm volatile("ldmatrix.sync.aligned.m8n8.x2.shared.b16 {%0,%1}, [%2];"
        : "=r"(r[0]), "=r"(r[1]) : "r"(addr));
}
__device__ __forceinline__ int bswz(int k, int n) {
    return n ^ (((k >> 2) & 7) << 2);
}
__device__ __forceinline__ void cp16(void* dst, const void* src) {
    uint32_t d;
    asm("{ .reg .u64 t; cvta.to.shared.u64 t, %1; cvt.u32.u64 %0, t; }" : "=r"(d) : "l"(dst));
    asm volatile("cp.async.cg.shared.global [%0], [%1], 16;" :: "r"(d), "l"(src));
}
#define CP_COMMIT() asm volatile("cp.async.commit_group;" ::: "memory")
#define CP_WAIT0()  asm volatile("cp.async.wait_group 0;" ::: "memory")

// proj BK=32 stage, BM=128/BN=128: 8 warps 4(m) x 2(n).
__device__ __forceinline__ void mma_stage(const uint32_t* As, const uint32_t* Bs,
                                          int wm, int wn, int lane,
                                          float acc[2][8][4])
{
    int g = lane >> 2, t = lane & 3;
    #pragma unroll
    for (int s = 0; s < 4; s++) {
        int k8 = s * 8;
        uint32_t a[2][4], b[8][2];
        #pragma unroll
        for (int mt = 0; mt < 2; mt++) {
            int r = wm * 32 + mt * 16 + g;
            a[mt][0] = As[r * ASTR + k8 + t];
            a[mt][1] = As[(r + 8) * ASTR + k8 + t];
            a[mt][2] = As[r * ASTR + k8 + t + 4];
            a[mt][3] = As[(r + 8) * ASTR + k8 + t + 4];
        }
        #pragma unroll
        for (int nt = 0; nt < 8; nt++) {
            int c = wn * 64 + nt * 8 + g;
            b[nt][0] = Bs[(k8 + t) * BSTR + bswz(k8 + t, c)];
            b[nt][1] = Bs[(k8 + t + 4) * BSTR + bswz(k8 + t + 4, c)];
        }
        #pragma unroll
        for (int mt = 0; mt < 2; mt++)
            #pragma unroll
            for (int nt = 0; nt < 8; nt++)
                mma8(acc[mt][nt], a[mt], b[nt]);
    }
}

// ===========================================================================
// Fused QKV projection via tf32 MMA.  V is written TRANSPOSED [b][dh][seq].
// ===========================================================================
__global__ __launch_bounds__(256, 2) void proj_kernel(
    const float* __restrict__ x0, const float* __restrict__ x1, const float* __restrict__ x2,
    const float* __restrict__ w0, const float* __restrict__ w1, const float* __restrict__ w2,
    const float* __restrict__ b0, const float* __restrict__ b1, const float* __restrict__ b2)
{
    __shared__ uint32_t As[128 * ASTR];
    __shared__ uint32_t Bs[32 * BSTR];

    int sel = blockIdx.y;
    const float* X    = sel == 0 ? x0 : (sel == 1 ? x1 : x2);
    const float* W    = sel == 0 ? w0 : (sel == 1 ? w1 : w2);
    const float* bias = sel == 0 ? b0 : (sel == 1 ? b1 : b2);

    int m0  = blockIdx.x * 128;
    int tid = threadIdx.x;
    int lane = tid & 31, wid = tid >> 5;
    int wm = wid & 3, wn = wid >> 2;

    float acc[2][8][4];
    #pragma unroll
    for (int i = 0; i < 2; i++)
        #pragma unroll
        for (int j = 0; j < 8; j++)
            #pragma unroll
            for (int q = 0; q < 4; q++) acc[i][j][q] = 0.f;

    for (int k0 = 0; k0 < DIN; k0 += 32) {
        #pragma unroll
        for (int it = 0; it < 4; it++) {
            int idx = tid + it * 256;
            int r = idx >> 3, c4 = idx & 7;
            float4 v = *(const float4*)(X + (size_t)(m0 + r) * DIN + k0 + c4 * 4);
            uint4 u = { f2tf(v.x), f2tf(v.y), f2tf(v.z), f2tf(v.w) };
            *(uint4*)&As[r * ASTR + c4 * 4] = u;
        }
        #pragma unroll
        for (int it = 0; it < 4; it++) {
            int idx = tid + it * 256;
            int r = idx >> 5, c4 = idx & 31;
            float4 v = *(const float4*)(W + (size_t)(k0 + r) * DH + c4 * 4);
            uint4 u = { f2tf(v.x), f2tf(v.y), f2tf(v.z), f2tf(v.w) };
            *(uint4*)&Bs[r * BSTR + bswz(r, c4 * 4)] = u;
        }
        __syncthreads();
        mma_stage(As, Bs, wm, wn, lane, acc);
        __syncthreads();
    }

    int g = lane >> 2, t = lane & 3;
    #pragma unroll
    for (int mt = 0; mt < 2; mt++) {
        int m = m0 + wm * 32 + mt * 16 + g;
        if (sel != 2) {
            float* Out = sel == 0 ? g_q : g_k;
            #pragma unroll
            for (int nt = 0; nt < 8; nt++) {
                int col = wn * 64 + nt * 8 + 2 * t;
                float bb0 = bias[col], bb1 = bias[col + 1];
                uint2 lo = { f2tf(acc[mt][nt][0] + bb0), f2tf(acc[mt][nt][1] + bb1) };
                uint2 hi = { f2tf(acc[mt][nt][2] + bb0), f2tf(acc[mt][nt][3] + bb1) };
                *(uint2*)(Out + (size_t)m * DH + col)       = lo;
                *(uint2*)(Out + (size_t)(m + 8) * DH + col) = hi;
            }
        } else {
            // V transposed: g_v[b][dh][s]
            int b = m >> 11, s = m & 2047;
            float* Vb = g_v + (size_t)b * DH * SEQ;
            #pragma unroll
            for (int nt = 0; nt < 8; nt++) {
                int col = wn * 64 + nt * 8 + 2 * t;
                float bb0 = bias[col], bb1 = bias[col + 1];
                Vb[(size_t)col * SEQ + s]           = __uint_as_float(f2tf(acc[mt][nt][0] + bb0));
                Vb[(size_t)(col + 1) * SEQ + s]     = __uint_as_float(f2tf(acc[mt][nt][1] + bb1));
                Vb[(size_t)col * SEQ + s + 8]       = __uint_as_float(f2tf(acc[mt][nt][2] + bb0));
                Vb[(size_t)(col + 1) * SEQ + s + 8] = __uint_as_float(f2tf(acc[mt][nt][3] + bb1));
            }
        }
    }
}

// ===========================================================================
// Flash attention, ldmatrix edition. BM=64 q-rows/block, TN=32 keys/iter.
// 8 warps 2(m) x 4(n). Pad-stride tiles (stride = 4 mod 32 words).
// Smem (u32 words):
//   Q  [0, 8448)       64 x 132
//   K  [8448, 12672)   32 x 132  (single buffer)
//   Vt [12672, 21888)  2 x (128 x 36)   (V transposed: rows = dh, cols = key)
//   P  [21888, 24192)  64 x 36
//   redm 24192 (4x64), reds 24448 (4x64)   total 24704 w = 98816 B
// ===========================================================================
#define FL_SMEM (24704 * 4)

__global__ __launch_bounds__(256, 2) void flash_kernel(float* __restrict__ Out)
{
    extern __shared__ uint32_t ds[];
    uint32_t sb = smem_u32(ds);
    float* redm = (float*)(ds + 24192);
    float* reds = (float*)(ds + 24448);

    int b  = blockIdx.y;
    int m0 = blockIdx.x * 64;
    const float* Qg = g_q + (size_t)b * SEQ * DH + (size_t)m0 * DH;
    const float* Kg = g_k + (size_t)b * SEQ * DH;
    const float* Vt = g_v + (size_t)b * DH * SEQ;
    float*       Ob = Out + (size_t)b * SEQ * DH + (size_t)m0 * DH;

    int tid = threadIdx.x, lane = tid & 31, wid = tid >> 5;
    int g = lane >> 2, t = lane & 3;
    int wm = wid & 1, wn = wid >> 1;

    // per-lane ldmatrix base addresses (bytes)
    int rA  = (lane & 7) + ((lane & 8) ? 8 : 0);
    int kwA = (lane & 16) ? 4 : 0;
    uint32_t qa0 = sb + (((wm * 32 +      rA) * 132 + kwA) << 2);
    uint32_t qa1 = sb + (((wm * 32 + 16 + rA) * 132 + kwA) << 2);
    uint32_t kb  = sb + ((8448 + (wn * 8 + (lane & 7)) * 132 + ((lane & 8) ? 4 : 0)) << 2);
    uint32_t pa0 = sb + ((21888 + (wm * 32 +      rA) * 36 + kwA) << 2);
    uint32_t pa1 = sb + ((21888 + (wm * 32 + 16 + rA) * 36 + kwA) << 2);
    int rV  = (lane & 7) + ((lane & 16) ? 8 : 0);
    int kwV = (lane & 8) ? 4 : 0;
    uint32_t vb0 = sb + ((12672 + (wn * 32 +      rV) * 36 + kwV) << 2);
    uint32_t vb1 = sb + ((12672 + (wn * 32 + 16 + rV) * 36 + kwV) << 2);

    // ---- prologue: Q (resident), K0, V0 ----
    #pragma unroll
    for (int it = 0; it < 8; it++) {
        int idx = tid + it * 256, r = idx >> 5, c = idx & 31;
        cp16(&ds[r * 132 + c * 4], Qg + (size_t)r * DH + c * 4);
    }
    #pragma unroll
    for (int it = 0; it < 4; it++) {
        int idx = tid + it * 256, r = idx >> 5, c = idx & 31;
        cp16(&ds[8448 + r * 132 + c * 4], Kg + (size_t)r * DH + c * 4);
    }
    #pragma unroll
    for (int it = 0; it < 4; it++) {
        int idx = tid + it * 256, r = idx >> 3, c = idx & 7;
        cp16(&ds[12672 + r * 36 + c * 4], Vt + (size_t)r * SEQ + c * 4);
    }
    CP_COMMIT();

    float m_run[2][2], l_run[2][2];
    #pragma unroll
    for (int i = 0; i < 2; i++)
        #pragma unroll
        for (int h = 0; h < 2; h++) { m_run[i][h] = -1e30f; l_run[i][h] = 0.f; }

    float o[2][4][4];
    #pragma unroll
    for (int i = 0; i < 2; i++)
        #pragma unroll
        for (int j = 0; j < 4; j++)
            #pragma unroll
            for (int q = 0; q < 4; q++) o[i][j][q] = 0.f;

    const float scaleQK = 0.08838834764831845f;  // 1/sqrt(128)

    for (int i = 0; i < SEQ / 32; i++) {
        int cur = i & 1;
        CP_WAIT0();
        __syncthreads();   // K(i), V(i) visible everywhere; PV(i-1) reads done

        if (i < SEQ / 32 - 1) {    // prefetch V(i+1) into the other buffer
            int k1 = (i + 1) * 32;
            uint32_t* Vn = ds + 12672 + (cur ^ 1) * 4608;
            #pragma unroll
            for (int it = 0; it < 4; it++) {
                int idx = tid + it * 256, r = idx >> 3, c = idx & 7;
                cp16(&Vn[r * 36 + c * 4], Vt + (size_t)r * SEQ + k1 + c * 4);
            }
            CP_COMMIT();
        }

        // ---- S = Q . K^T  (warp: rows wm*32..+31, cols wn*8..+7) ----
        float s_[2][4];
        #pragma unroll
        for (int mt = 0; mt < 2; mt++)
            #pragma unroll
            for (int q = 0; q < 4; q++) s_[mt][q] = 0.f;

        #pragma unroll
        for (int ks = 0; ks < 16; ks++) {
            uint32_t A0[4], A1[4], B0[2];
            ldsm4(A0, qa0 + ks * 32);
            ldsm4(A1, qa1 + ks * 32);
            ldsm2(B0, kb + ks * 32);
            mma8(s_[0], A0, B0);
            mma8(s_[1], A1, B0);
        }
        #pragma unroll
        for (int mt = 0; mt < 2; mt++)
            #pragma unroll
            for (int q = 0; q < 4; q++) s_[mt][q] *= scaleQK;

        // ---- per-row tile max ----
        #pragma unroll
        for (int mt = 0; mt < 2; mt++) {
            float p0 = fmaxf(s_[mt][0], s_[mt][1]);
            float p1 = fmaxf(s_[mt][2], s_[mt][3]);
            p0 = fmaxf(p0, __shfl_xor_sync(0xffffffffu, p0, 1));
            p0 = fmaxf(p0, __shfl_xor_sync(0xffffffffu, p0, 2));
            p1 = fmaxf(p1, __shfl_xor_sync(0xffffffffu, p1, 1));
            p1 = fmaxf(p1, __shfl_xor_sync(0xffffffffu, p1, 2));
            if (t == 0) {
                redm[wn * 64 + wm * 32 + mt * 16 + g]     = p0;
                redm[wn * 64 + wm * 32 + mt * 16 + g + 8] = p1;
            }
        }
        __syncthreads();   // Y: redm ready; all warps done reading K

        if (i < SEQ / 32 - 1) {    // prefetch K(i+1) into the single K buffer
            int k1 = (i + 1) * 32;
            #pragma unroll
            for (int it = 0; it < 4; it++) {
                int idx = tid + it * 256, r = idx >> 5, c = idx & 31;
                cp16(&ds[8448 + r * 132 + c * 4], Kg + (size_t)(k1 + r) * DH + c * 4);
            }
            CP_COMMIT();
        }

        float sc[2][2];
        #pragma unroll
        for (int mt = 0; mt < 2; mt++)
            #pragma unroll
            for (int h = 0; h < 2; h++) {
                int r = wm * 32 + mt * 16 + h * 8 + g;
                float tm = fmaxf(fmaxf(redm[r], redm[64 + r]),
                                 fmaxf(redm[128 + r], redm[192 + r]));
                float mn = fmaxf(m_run[mt][h], tm);
                sc[mt][h] = __expf(m_run[mt][h] - mn);
                m_run[mt][h] = mn;
            }

        // ---- P = exp(s - m) -> Ps; partial row sums -> reds ----
        #pragma unroll
        for (int mt = 0; mt < 2; mt++) {
            float e0 = __expf(s_[mt][0] - m_run[mt][0]);
            float e1 = __expf(s_[mt][1] - m_run[mt][0]);
            float e2 = __expf(s_[mt][2] - m_run[mt][1]);
            float e3 = __expf(s_[mt][3] - m_run[mt][1]);
            int r = wm * 32 + mt * 16 + g;
            uint2 u0 = { f2tf(e0), f2tf(e1) };
            uint2 u1 = { f2tf(e2), f2tf(e3) };
            *(uint2*)&ds[21888 + r * 36 + wn * 8 + 2 * t]       = u0;
            *(uint2*)&ds[21888 + (r + 8) * 36 + wn * 8 + 2 * t] = u1;
            float q0 = e0 + e1, q1 = e2 + e3;
            q0 += __shfl_xor_sync(0xffffffffu, q0, 1);
            q0 += __shfl_xor_sync(0xffffffffu, q0, 2);
            q1 += __shfl_xor_sync(0xffffffffu, q1, 1);
            q1 += __shfl_xor_sync(0xffffffffu, q1, 2);
            if (t == 0) {
                reds[wn * 64 + r]     = q0;
                reds[wn * 64 + r + 8] = q1;
            }
        }

        // ---- rescale O while stores land ----
        #pragma unroll
        for (int mt = 0; mt < 2; mt++)
            #pragma unroll
            for (int nt = 0; nt < 4; nt++) {
                o[mt][nt][0] *= sc[mt][0];
                o[mt][nt][1] *= sc[mt][0];
                o[mt][nt][2] *= sc[mt][1];
                o[mt][nt][3] *= sc[mt][1];
            }
        __syncthreads();   // Z: P + reds visible

        #pragma unroll
        for (int mt = 0; mt < 2; mt++)
            #pragma unroll
            for (int h = 0; h < 2; h++) {
                int r = wm * 32 + mt * 16 + h * 8 + g;
                float ts = reds[r] + reds[64 + r] + reds[128 + r] + reds[192 + r];
                l_run[mt][h] = l_run[mt][h] * sc[mt][h] + ts;
            }

        // ---- O += P . V   (warp: rows wm*32..+31, dh cols wn*32..+31) ----
        uint32_t vc0 = vb0 + cur * 18432;   // 4608 words * 4 B
        uint32_t vc1 = vb1 + cur * 18432;
        #pragma unroll
        for (int ks = 0; ks < 4; ks++) {
            uint32_t P0[4], P1[4], Bv[2][4];
            ldsm4(P0, pa0 + ks * 32);
            ldsm4(P1, pa1 + ks * 32);
            ldsm4(Bv[0], vc0 + ks * 32);   // {b0,b1} n-tile0, {b0,b1} n-tile1
            ldsm4(Bv[1], vc1 + ks * 32);   // n-tiles 2,3
            #pragma unroll
            for (int nt = 0; nt < 4; nt++) {
                const uint32_t* bv = &Bv[nt >> 1][(nt & 1) * 2];
                mma8(o[0][nt], P0, bv);
                mma8(o[1][nt], P1, bv);
            }
        }
    }

    // ---- epilogue: O / l -> gmem ----
    float inv[2][2];
    #pragma unroll
    for (int mt = 0; mt < 2; mt++)
        #pragma unroll
        for (int h = 0; h < 2; h++) inv[mt][h] = 1.0f / l_run[mt][h];

    #pragma unroll
    for (int mt = 0; mt < 2; mt++) {
        int row = wm * 32 + mt * 16 + g;
        #pragma unroll
        for (int nt = 0; nt < 4; nt++) {
            int col = wn * 32 + nt * 8 + 2 * t;
            float2 lo = { o[mt][nt][0] * inv[mt][0], o[mt][nt][1] * inv[mt][0] };
            float2 hi = { o[mt][nt][2] * inv[mt][1], o[mt][nt][3] * inv[mt][1] };
            *(float2*)(Ob + (size_t)row * DH + col)       = lo;
            *(float2*)(Ob + (size_t)(row + 8) * DH + col) = hi;
        }
    }
}

// ===========================================================================
extern "C" void kernel_launch(void* const* d_in, const int* in_sizes, int n_in,
                              void* d_out, int out_size)
{
    const float* q_in = (const float*)d_in[0];
    const float* k_in = (const float*)d_in[1];
    const float* v_in = (const float*)d_in[2];
    const float* Wq   = (const float*)d_in[3];
    const float* Wk   = (const float*)d_in[4];
    const float* Wv   = (const float*)d_in[5];
    const float* bq   = (const float*)d_in[6];
    const float* bk   = (const float*)d_in[7];
    const float* bv   = (const float*)d_in[8];
    float* out        = (float*)d_out;

    static bool attr_done = false;
    if (!attr_done) {
        cudaFuncSetAttribute(flash_kernel, cudaFuncAttributeMaxDynamicSharedMemorySize, FL_SMEM);
        attr_done = true;
    }

    proj_kernel<<<dim3(MTOT / 128, 3), 256>>>(q_in, k_in, v_in, Wq, Wk, Wv, bq, bk, bv);
    flash_kernel<<<dim3(SEQ / 64, NB), 256, FL_SMEM>>>(out);
}

// round 12
// speedup vs baseline: 1.4806x; 1.3387x over previous
#include <cuda_runtime.h>
#include <cstdint>

#define NB 8
#define SEQ 2048
#define DIN 512
#define DH 128
#define MTOT (NB*SEQ)

#define ASTR 36    // proj A smem row stride
#define BSTR 136   // proj B smem row stride

// Scratch (device globals: allocation-free rule)
__device__ float g_q[MTOT*DH];
__device__ float g_k[MTOT*DH];
__device__ float g_v[MTOT*DH];   // TRANSPOSED: [b][dh][seq]

// ---------------------------------------------------------------------------
// helpers (baseline sm_75/sm_80 ISA only)
// ---------------------------------------------------------------------------
__device__ __forceinline__ uint32_t smem_u32(const void* p) {
    uint32_t a;
    asm("{ .reg .u64 t; cvta.to.shared.u64 t, %1; cvt.u32.u64 %0, t; }" : "=r"(a) : "l"(p));
    return a;
}
__device__ __forceinline__ uint32_t f2tf(float x) {
    uint32_t u;
    asm("cvt.rna.tf32.f32 %0, %1;" : "=r"(u) : "f"(x));
    return u;
}
__device__ __forceinline__ void mma8(float* c, const uint32_t* a, const uint32_t* b) {
    asm volatile(
        "mma.sync.aligned.m16n8k8.row.col.f32.tf32.tf32.f32 "
        "{%0,%1,%2,%3}, {%4,%5,%6,%7}, {%8,%9}, {%0,%1,%2,%3};"
        : "+f"(c[0]), "+f"(c[1]), "+f"(c[2]), "+f"(c[3])
        : "r"(a[0]), "r"(a[1]), "r"(a[2]), "r"(a[3]), "r"(b[0]), "r"(b[1]));
}
__device__ __forceinline__ void ldsm4(uint32_t* r, uint32_t addr) {
    asm volatile("ldmatrix.sync.aligned.m8n8.x4.shared.b16 {%0,%1,%2,%3}, [%4];"
        : "=r"(r[0]), "=r"(r[1]), "=r"(r[2]), "=r"(r[3]) : "r"(addr));
}
__device__ __forceinline__ int bswz(int k, int n) {
    return n ^ (((k >> 2) & 7) << 2);
}
__device__ __forceinline__ void cp16(void* dst, const void* src) {
    uint32_t d;
    asm("{ .reg .u64 t; cvta.to.shared.u64 t, %1; cvt.u32.u64 %0, t; }" : "=r"(d) : "l"(dst));
    asm volatile("cp.async.cg.shared.global [%0], [%1], 16;" :: "r"(d), "l"(src));
}
#define CP_COMMIT() asm volatile("cp.async.commit_group;" ::: "memory")
#define CP_WAIT0()  asm volatile("cp.async.wait_group 0;" ::: "memory")

// proj BK=32 stage, BM=128/BN=128: 8 warps 4(m) x 2(n).
__device__ __forceinline__ void mma_stage(const uint32_t* As, const uint32_t* Bs,
                                          int wm, int wn, int lane,
                                          float acc[2][8][4])
{
    int g = lane >> 2, t = lane & 3;
    #pragma unroll
    for (int s = 0; s < 4; s++) {
        int k8 = s * 8;
        uint32_t a[2][4], b[8][2];
        #pragma unroll
        for (int mt = 0; mt < 2; mt++) {
            int r = wm * 32 + mt * 16 + g;
            a[mt][0] = As[r * ASTR + k8 + t];
            a[mt][1] = As[(r + 8) * ASTR + k8 + t];
            a[mt][2] = As[r * ASTR + k8 + t + 4];
            a[mt][3] = As[(r + 8) * ASTR + k8 + t + 4];
        }
        #pragma unroll
        for (int nt = 0; nt < 8; nt++) {
            int c = wn * 64 + nt * 8 + g;
            b[nt][0] = Bs[(k8 + t) * BSTR + bswz(k8 + t, c)];
            b[nt][1] = Bs[(k8 + t + 4) * BSTR + bswz(k8 + t + 4, c)];
        }
        #pragma unroll
        for (int mt = 0; mt < 2; mt++)
            #pragma unroll
            for (int nt = 0; nt < 8; nt++)
                mma8(acc[mt][nt], a[mt], b[nt]);
    }
}

// ===========================================================================
// Fused QKV projection via tf32 MMA.  V is written TRANSPOSED [b][dh][seq].
// ===========================================================================
__global__ __launch_bounds__(256, 2) void proj_kernel(
    const float* __restrict__ x0, const float* __restrict__ x1, const float* __restrict__ x2,
    const float* __restrict__ w0, const float* __restrict__ w1, const float* __restrict__ w2,
    const float* __restrict__ b0, const float* __restrict__ b1, const float* __restrict__ b2)
{
    __shared__ uint32_t As[128 * ASTR];
    __shared__ uint32_t Bs[32 * BSTR];

    int sel = blockIdx.y;
    const float* X    = sel == 0 ? x0 : (sel == 1 ? x1 : x2);
    const float* W    = sel == 0 ? w0 : (sel == 1 ? w1 : w2);
    const float* bias = sel == 0 ? b0 : (sel == 1 ? b1 : b2);

    int m0  = blockIdx.x * 128;
    int tid = threadIdx.x;
    int lane = tid & 31, wid = tid >> 5;
    int wm = wid & 3, wn = wid >> 2;

    float acc[2][8][4];
    #pragma unroll
    for (int i = 0; i < 2; i++)
        #pragma unroll
        for (int j = 0; j < 8; j++)
            #pragma unroll
            for (int q = 0; q < 4; q++) acc[i][j][q] = 0.f;

    for (int k0 = 0; k0 < DIN; k0 += 32) {
        #pragma unroll
        for (int it = 0; it < 4; it++) {
            int idx = tid + it * 256;
            int r = idx >> 3, c4 = idx & 7;
            float4 v = *(const float4*)(X + (size_t)(m0 + r) * DIN + k0 + c4 * 4);
            uint4 u = { f2tf(v.x), f2tf(v.y), f2tf(v.z), f2tf(v.w) };
            *(uint4*)&As[r * ASTR + c4 * 4] = u;
        }
        #pragma unroll
        for (int it = 0; it < 4; it++) {
            int idx = tid + it * 256;
            int r = idx >> 5, c4 = idx & 31;
            float4 v = *(const float4*)(W + (size_t)(k0 + r) * DH + c4 * 4);
            uint4 u = { f2tf(v.x), f2tf(v.y), f2tf(v.z), f2tf(v.w) };
            *(uint4*)&Bs[r * BSTR + bswz(r, c4 * 4)] = u;
        }
        __syncthreads();
        mma_stage(As, Bs, wm, wn, lane, acc);
        __syncthreads();
    }

    int g = lane >> 2, t = lane & 3;
    #pragma unroll
    for (int mt = 0; mt < 2; mt++) {
        int m = m0 + wm * 32 + mt * 16 + g;
        if (sel != 2) {
            float* Out = sel == 0 ? g_q : g_k;
            #pragma unroll
            for (int nt = 0; nt < 8; nt++) {
                int col = wn * 64 + nt * 8 + 2 * t;
                float bb0 = bias[col], bb1 = bias[col + 1];
                uint2 lo = { f2tf(acc[mt][nt][0] + bb0), f2tf(acc[mt][nt][1] + bb1) };
                uint2 hi = { f2tf(acc[mt][nt][2] + bb0), f2tf(acc[mt][nt][3] + bb1) };
                *(uint2*)(Out + (size_t)m * DH + col)       = lo;
                *(uint2*)(Out + (size_t)(m + 8) * DH + col) = hi;
            }
        } else {
            int b = m >> 11, s = m & 2047;
            float* Vb = g_v + (size_t)b * DH * SEQ;
            #pragma unroll
            for (int nt = 0; nt < 8; nt++) {
                int col = wn * 64 + nt * 8 + 2 * t;
                float bb0 = bias[col], bb1 = bias[col + 1];
                Vb[(size_t)col * SEQ + s]           = __uint_as_float(f2tf(acc[mt][nt][0] + bb0));
                Vb[(size_t)(col + 1) * SEQ + s]     = __uint_as_float(f2tf(acc[mt][nt][1] + bb1));
                Vb[(size_t)col * SEQ + s + 8]       = __uint_as_float(f2tf(acc[mt][nt][2] + bb0));
                Vb[(size_t)(col + 1) * SEQ + s + 8] = __uint_as_float(f2tf(acc[mt][nt][3] + bb1));
            }
        }
    }
}

// ===========================================================================
// Flash attention, FA2-style. 4 warps/block, warp owns 16 q-rows.
// BM=64, TN=32 keys/iter. Q in registers; P via in-quad shuffles;
// softmax fully warp-local; ONE barrier per iteration.
// Smem (u32 words): K0 @0 (32x132=4224), K1 @4224,
//                   V0 @8448 (128x36=4608), V1 @13056.  Total 17664 w.
// Q staged once at [0, 8448) before K loads.
// ===========================================================================
#define FL_SMEM (17664 * 4)

__global__ __launch_bounds__(128, 2) void flash_kernel(float* __restrict__ Out)
{
    extern __shared__ uint32_t ds[];
    uint32_t sb = smem_u32(ds);

    int b  = blockIdx.y;
    int m0 = blockIdx.x * 64;
    const float* Qg = g_q + (size_t)b * SEQ * DH + (size_t)m0 * DH;
    const float* Kg = g_k + (size_t)b * SEQ * DH;
    const float* Vt = g_v + (size_t)b * DH * SEQ;
    float*       Ob = Out + (size_t)b * SEQ * DH + (size_t)m0 * DH;

    int tid = threadIdx.x, lane = tid & 31, wq = tid >> 5;
    int g = lane >> 2, t = lane & 3;

    // ---- stage Q once, lift into registers ----
    #pragma unroll
    for (int it = 0; it < 16; it++) {
        int idx = tid + it * 128, r = idx >> 5, c = idx & 31;
        cp16(&ds[r * 132 + c * 4], Qg + (size_t)r * DH + c * 4);
    }
    CP_COMMIT(); CP_WAIT0(); __syncthreads();

    int rA  = (lane & 7) + ((lane & 8) ? 8 : 0);
    int kwA = (lane & 16) ? 4 : 0;
    uint32_t qa = sb + (((wq * 16 + rA) * 132 + kwA) << 2);
    uint32_t q[16][4];
    #pragma unroll
    for (int ks = 0; ks < 16; ks++) ldsm4(q[ks], qa + ks * 32);
    __syncthreads();   // staging free before K overwrites it

    // ---- K0 / V0 ----
    #pragma unroll
    for (int it = 0; it < 8; it++) {
        int idx = tid + it * 128, r = idx >> 5, c = idx & 31;
        cp16(&ds[r * 132 + c * 4], Kg + (size_t)r * DH + c * 4);
    }
    #pragma unroll
    for (int it = 0; it < 8; it++) {
        int idx = tid + it * 128, r = idx >> 3, c = idx & 7;
        cp16(&ds[8448 + r * 36 + c * 4], Vt + (size_t)r * SEQ + c * 4);
    }
    CP_COMMIT();

    // per-lane ldmatrix offsets for K (B-frags, 2 n-tiles per ldsm4) and V
    int rB  = (lane & 7) + ((lane & 16) ? 8 : 0);
    int kwB = (lane & 8) ? 4 : 0;
    uint32_t kb_off = (uint32_t)(rB * 132 + kwB);
    uint32_t vb_off = (uint32_t)(rB * 36 + kwB);

    float m0r = -1e30f, m1r = -1e30f, l0 = 0.f, l1 = 0.f;
    float o[16][4];
    #pragma unroll
    for (int i = 0; i < 16; i++)
        #pragma unroll
        for (int qd = 0; qd < 4; qd++) o[i][qd] = 0.f;

    const float scaleQK = 0.08838834764831845f;  // 1/sqrt(128)
    int srcA = (lane & ~3) | (t >> 1);
    int srcB = srcA + 2;

    for (int i = 0; i < SEQ / 32; i++) {
        int cur = i & 1;
        CP_WAIT0();
        __syncthreads();   // K(i)/V(i) ready; all warps past iter i-1

        if (i < SEQ / 32 - 1) {
            int k1 = (i + 1) * 32;
            uint32_t* Kn = ds + (cur ^ 1) * 4224;
            uint32_t* Vn = ds + 8448 + (cur ^ 1) * 4608;
            #pragma unroll
            for (int it = 0; it < 8; it++) {
                int idx = tid + it * 128, r = idx >> 5, c = idx & 31;
                cp16(&Kn[r * 132 + c * 4], Kg + (size_t)(k1 + r) * DH + c * 4);
            }
            #pragma unroll
            for (int it = 0; it < 8; it++) {
                int idx = tid + it * 128, r = idx >> 3, c = idx & 7;
                cp16(&Vn[r * 36 + c * 4], Vt + (size_t)r * SEQ + k1 + c * 4);
            }
            CP_COMMIT();
        }

        uint32_t Kb = sb + ((cur * 4224) << 2);
        uint32_t Vb = sb + ((8448 + cur * 4608) << 2);

        // ---- S = Q . K^T : warp rows wq*16..+15, all 32 keys ----
        float s_[4][4];
        #pragma unroll
        for (int j = 0; j < 4; j++)
            #pragma unroll
            for (int qd = 0; qd < 4; qd++) s_[j][qd] = 0.f;

        #pragma unroll
        for (int ks = 0; ks < 16; ks++) {
            uint32_t B0[4], B1[4];
            ldsm4(B0, Kb + ((kb_off + ks * 8) << 2));            // n-tiles 0,1
            ldsm4(B1, Kb + ((kb_off + 2112 + ks * 8) << 2));     // n-tiles 2,3 (16*132)
            mma8(s_[0], q[ks], B0);
            mma8(s_[1], q[ks], B0 + 2);
            mma8(s_[2], q[ks], B1);
            mma8(s_[3], q[ks], B1 + 2);
        }
        #pragma unroll
        for (int j = 0; j < 4; j++)
            #pragma unroll
            for (int qd = 0; qd < 4; qd++) s_[j][qd] *= scaleQK;

        // ---- warp-local online softmax (rows g and g+8) ----
        float mx0 = -1e30f, mx1 = -1e30f;
        #pragma unroll
        for (int j = 0; j < 4; j++) {
            mx0 = fmaxf(mx0, fmaxf(s_[j][0], s_[j][1]));
            mx1 = fmaxf(mx1, fmaxf(s_[j][2], s_[j][3]));
        }
        mx0 = fmaxf(mx0, __shfl_xor_sync(0xffffffffu, mx0, 1));
        mx0 = fmaxf(mx0, __shfl_xor_sync(0xffffffffu, mx0, 2));
        mx1 = fmaxf(mx1, __shfl_xor_sync(0xffffffffu, mx1, 1));
        mx1 = fmaxf(mx1, __shfl_xor_sync(0xffffffffu, mx1, 2));

        float mn0 = fmaxf(m0r, mx0), mn1 = fmaxf(m1r, mx1);
        float sc0 = __expf(m0r - mn0), sc1 = __expf(m1r - mn1);
        m0r = mn0; m1r = mn1;

        uint32_t p[4][4];
        float ts0 = 0.f, ts1 = 0.f;
        #pragma unroll
        for (int j = 0; j < 4; j++) {
            float e0 = __expf(s_[j][0] - mn0);
            float e1 = __expf(s_[j][1] - mn0);
            float e2 = __expf(s_[j][2] - mn1);
            float e3 = __expf(s_[j][3] - mn1);
            ts0 += e0 + e1; ts1 += e2 + e3;
            p[j][0] = f2tf(e0); p[j][1] = f2tf(e1);
            p[j][2] = f2tf(e2); p[j][3] = f2tf(e3);
        }
        ts0 += __shfl_xor_sync(0xffffffffu, ts0, 1);
        ts0 += __shfl_xor_sync(0xffffffffu, ts0, 2);
        ts1 += __shfl_xor_sync(0xffffffffu, ts1, 1);
        ts1 += __shfl_xor_sync(0xffffffffu, ts1, 2);
        l0 = l0 * sc0 + ts0;
        l1 = l1 * sc1 + ts1;

        // ---- rescale O ----
        #pragma unroll
        for (int nt = 0; nt < 16; nt++) {
            o[nt][0] *= sc0; o[nt][1] *= sc0;
            o[nt][2] *= sc1; o[nt][3] *= sc1;
        }

        // ---- O += P . V  (A-frags from in-quad shuffles of p) ----
        #pragma unroll
        for (int ks = 0; ks < 4; ks++) {
            uint32_t x0 = __shfl_sync(0xffffffffu, p[ks][0], srcA);
            uint32_t x1 = __shfl_sync(0xffffffffu, p[ks][1], srcA);
            uint32_t x2 = __shfl_sync(0xffffffffu, p[ks][2], srcA);
            uint32_t x3 = __shfl_sync(0xffffffffu, p[ks][3], srcA);
            uint32_t y0 = __shfl_sync(0xffffffffu, p[ks][0], srcB);
            uint32_t y1 = __shfl_sync(0xffffffffu, p[ks][1], srcB);
            uint32_t y2 = __shfl_sync(0xffffffffu, p[ks][2], srcB);
            uint32_t y3 = __shfl_sync(0xffffffffu, p[ks][3], srcB);
            uint32_t A[4];
            A[0] = (t & 1) ? x1 : x0;   // row g,   col t
            A[1] = (t & 1) ? x3 : x2;   // row g+8, col t
            A[2] = (t & 1) ? y1 : y0;   // row g,   col t+4
            A[3] = (t & 1) ? y3 : y2;   // row g+8, col t+4
            #pragma unroll
            for (int p8 = 0; p8 < 8; p8++) {
                uint32_t Bv[4];
                ldsm4(Bv, Vb + ((vb_off + (uint32_t)(p8 * 16 * 36 + ks * 8)) << 2));
                mma8(o[p8 * 2],     A, Bv);
                mma8(o[p8 * 2 + 1], A, Bv + 2);
            }
        }
    }

    // ---- epilogue: O / l ----
    float i0 = 1.0f / l0, i1 = 1.0f / l1;
    int row0 = wq * 16 + g, row1 = row0 + 8;
    #pragma unroll
    for (int nt = 0; nt < 16; nt++) {
        int col = nt * 8 + 2 * t;
        float2 lo = { o[nt][0] * i0, o[nt][1] * i0 };
        float2 hi = { o[nt][2] * i1, o[nt][3] * i1 };
        *(float2*)(Ob + (size_t)row0 * DH + col) = lo;
        *(float2*)(Ob + (size_t)row1 * DH + col) = hi;
    }
}

// ===========================================================================
extern "C" void kernel_launch(void* const* d_in, const int* in_sizes, int n_in,
                              void* d_out, int out_size)
{
    const float* q_in = (const float*)d_in[0];
    const float* k_in = (const float*)d_in[1];
    const float* v_in = (const float*)d_in[2];
    const float* Wq   = (const float*)d_in[3];
    const float* Wk   = (const float*)d_in[4];
    const float* Wv   = (const float*)d_in[5];
    const float* bq   = (const float*)d_in[6];
    const float* bk   = (const float*)d_in[7];
    const float* bv   = (const float*)d_in[8];
    float* out        = (float*)d_out;

    static bool attr_done = false;
    if (!attr_done) {
        cudaFuncSetAttribute(flash_kernel, cudaFuncAttributeMaxDynamicSharedMemorySize, FL_SMEM);
        attr_done = true;
    }

    proj_kernel<<<dim3(MTOT / 128, 3), 256>>>(q_in, k_in, v_in, Wq, Wk, Wv, bq, bk, bv);
    flash_kernel<<<dim3(SEQ / 64, NB), 128, FL_SMEM>>>(out);
}

// round 13
// speedup vs baseline: 1.7050x; 1.1515x over previous
#include <cuda_runtime.h>
#include <cstdint>

#define NB 8
#define SEQ 2048
#define DIN 512
#define DH 128
#define MTOT (NB*SEQ)

// Scratch (device globals: allocation-free rule)
__device__ float g_q[MTOT*DH];
__device__ float g_k[MTOT*DH];
__device__ float g_v[MTOT*DH];   // TRANSPOSED: [b][dh][seq]
__device__ float g_wt[3*DH*DIN]; // W tf32-rounded, transposed: [sel][n][k]

// ---------------------------------------------------------------------------
// helpers (baseline sm_75/sm_80 ISA only)
// ---------------------------------------------------------------------------
__device__ __forceinline__ uint32_t smem_u32(const void* p) {
    uint32_t a;
    asm("{ .reg .u64 t; cvta.to.shared.u64 t, %1; cvt.u32.u64 %0, t; }" : "=r"(a) : "l"(p));
    return a;
}
__device__ __forceinline__ uint32_t f2tf(float x) {
    uint32_t u;
    asm("cvt.rna.tf32.f32 %0, %1;" : "=r"(u) : "f"(x));
    return u;
}
__device__ __forceinline__ void mma8(float* c, const uint32_t* a, const uint32_t* b) {
    asm volatile(
        "mma.sync.aligned.m16n8k8.row.col.f32.tf32.tf32.f32 "
        "{%0,%1,%2,%3}, {%4,%5,%6,%7}, {%8,%9}, {%0,%1,%2,%3};"
        : "+f"(c[0]), "+f"(c[1]), "+f"(c[2]), "+f"(c[3])
        : "r"(a[0]), "r"(a[1]), "r"(a[2]), "r"(a[3]), "r"(b[0]), "r"(b[1]));
}
__device__ __forceinline__ void ldsm4(uint32_t* r, uint32_t addr) {
    asm volatile("ldmatrix.sync.aligned.m8n8.x4.shared.b16 {%0,%1,%2,%3}, [%4];"
        : "=r"(r[0]), "=r"(r[1]), "=r"(r[2]), "=r"(r[3]) : "r"(addr));
}
__device__ __forceinline__ void cp16(void* dst, const void* src) {
    uint32_t d;
    asm("{ .reg .u64 t; cvta.to.shared.u64 t, %1; cvt.u32.u64 %0, t; }" : "=r"(d) : "l"(dst));
    asm volatile("cp.async.cg.shared.global [%0], [%1], 16;" :: "r"(d), "l"(src));
}
#define CP_COMMIT() asm volatile("cp.async.commit_group;" ::: "memory")
#define CP_WAIT1()  asm volatile("cp.async.wait_group 1;" ::: "memory")
#define CP_WAIT0()  asm volatile("cp.async.wait_group 0;" ::: "memory")

// ===========================================================================
// wprep: round W to tf32 and transpose into g_wt[sel][n][k].
// ===========================================================================
__global__ __launch_bounds__(256) void wprep_kernel(
    const float* __restrict__ w0, const float* __restrict__ w1, const float* __restrict__ w2)
{
    int sel = blockIdx.y;
    const float* W  = sel == 0 ? w0 : (sel == 1 ? w1 : w2);
    float*       Wt = g_wt + (size_t)sel * DH * DIN;
    int idx = blockIdx.x * 256 + threadIdx.x;     // 0..16383
    int k = idx >> 5, n4 = (idx & 31) * 4;
    float4 v = *(const float4*)(W + (size_t)k * DH + n4);
    Wt[(size_t)(n4 + 0) * DIN + k] = __uint_as_float(f2tf(v.x));
    Wt[(size_t)(n4 + 1) * DIN + k] = __uint_as_float(f2tf(v.y));
    Wt[(size_t)(n4 + 2) * DIN + k] = __uint_as_float(f2tf(v.z));
    Wt[(size_t)(n4 + 3) * DIN + k] = __uint_as_float(f2tf(v.w));
}

// ===========================================================================
// proj: Out = round_tf32(X*W + bias).  cp.async double-buffered, ldmatrix
// fragments.  BM=128, BN=128(full), BK=32, 16 stages.  8 warps 4(m) x 2(n).
// Smem (u32 words): X[2] @0 (128*36=4608 each), Wt[2] @9216.  18432 w.
// V (sel==2) written TRANSPOSED to g_v[b][dh][s].
// ===========================================================================
#define PJ_SMEM (18432 * 4)

__global__ __launch_bounds__(256, 2) void proj_kernel(
    const float* __restrict__ x0, const float* __restrict__ x1, const float* __restrict__ x2,
    const float* __restrict__ b0, const float* __restrict__ b1, const float* __restrict__ b2)
{
    extern __shared__ uint32_t ds[];
    uint32_t sb = smem_u32(ds);

    int sel = blockIdx.y;
    const float* X    = sel == 0 ? x0 : (sel == 1 ? x1 : x2);
    const float* bias = sel == 0 ? b0 : (sel == 1 ? b1 : b2);
    const float* Wt   = g_wt + (size_t)sel * DH * DIN;

    int m0  = blockIdx.x * 128;
    int tid = threadIdx.x;
    int lane = tid & 31, wid = tid >> 5;
    int wm = wid & 3, wn = wid >> 2;
    int g = lane >> 2, t = lane & 3;

    // ldmatrix per-lane bases
    int rA  = (lane & 7) + ((lane & 8) ? 8 : 0);
    int kwA = (lane & 16) ? 4 : 0;
    int rB  = (lane & 7) + ((lane & 16) ? 8 : 0);
    int kwB = (lane & 8) ? 4 : 0;

    float acc[2][8][4];
    #pragma unroll
    for (int i = 0; i < 2; i++)
        #pragma unroll
        for (int j = 0; j < 8; j++)
            #pragma unroll
            for (int q = 0; q < 4; q++) acc[i][j][q] = 0.f;

    // prologue: stage 0
    #pragma unroll
    for (int it = 0; it < 4; it++) {
        int idx = tid + it * 256, r = idx >> 3, c = idx & 7;
        cp16(&ds[r * 36 + c * 4],        X  + (size_t)(m0 + r) * DIN + c * 4);
        cp16(&ds[9216 + r * 36 + c * 4], Wt + (size_t)r * DIN + c * 4);
    }
    CP_COMMIT();

    for (int i = 0; i < 16; i++) {
        int cur = i & 1;
        if (i < 15) {
            int k1 = (i + 1) * 32;
            uint32_t* Xn = ds + (cur ^ 1) * 4608;
            uint32_t* Wn = ds + 9216 + (cur ^ 1) * 4608;
            #pragma unroll
            for (int it = 0; it < 4; it++) {
                int idx = tid + it * 256, r = idx >> 3, c = idx & 7;
                cp16(&Xn[r * 36 + c * 4], X  + (size_t)(m0 + r) * DIN + k1 + c * 4);
                cp16(&Wn[r * 36 + c * 4], Wt + (size_t)r * DIN + k1 + c * 4);
            }
            CP_COMMIT();
            CP_WAIT1();
        } else {
            CP_WAIT0();
        }
        __syncthreads();

        uint32_t Xb = sb + ((cur * 4608) << 2);
        uint32_t Wb = sb + ((9216 + cur * 4608) << 2);

        // A-frags (raw fp32 -> rna tf32 on regs)
        uint32_t af[2][4][4];
        #pragma unroll
        for (int mt = 0; mt < 2; mt++)
            #pragma unroll
            for (int ks = 0; ks < 4; ks++) {
                ldsm4(af[mt][ks], Xb + (((wm * 32 + mt * 16 + rA) * 36 + ks * 8 + kwA) << 2));
                #pragma unroll
                for (int j = 0; j < 4; j++)
                    af[mt][ks][j] = f2tf(__uint_as_float(af[mt][ks][j]));
            }
        // B-frags per k8 step + MMAs
        #pragma unroll
        for (int ks = 0; ks < 4; ks++) {
            uint32_t bf[4][4];
            #pragma unroll
            for (int p = 0; p < 4; p++)
                ldsm4(bf[p], Wb + (((wn * 64 + p * 16 + rB) * 36 + ks * 8 + kwB) << 2));
            #pragma unroll
            for (int mt = 0; mt < 2; mt++)
                #pragma unroll
                for (int nt = 0; nt < 8; nt++)
                    mma8(acc[mt][nt], af[mt][ks], &bf[nt >> 1][(nt & 1) * 2]);
        }
        __syncthreads();
    }

    // epilogue (identical mapping to round 12)
    #pragma unroll
    for (int mt = 0; mt < 2; mt++) {
        int m = m0 + wm * 32 + mt * 16 + g;
        if (sel != 2) {
            float* Out = sel == 0 ? g_q : g_k;
            #pragma unroll
            for (int nt = 0; nt < 8; nt++) {
                int col = wn * 64 + nt * 8 + 2 * t;
                float bb0 = bias[col], bb1 = bias[col + 1];
                uint2 lo = { f2tf(acc[mt][nt][0] + bb0), f2tf(acc[mt][nt][1] + bb1) };
                uint2 hi = { f2tf(acc[mt][nt][2] + bb0), f2tf(acc[mt][nt][3] + bb1) };
                *(uint2*)(Out + (size_t)m * DH + col)       = lo;
                *(uint2*)(Out + (size_t)(m + 8) * DH + col) = hi;
            }
        } else {
            int b = m >> 11, s = m & 2047;
            float* Vb = g_v + (size_t)b * DH * SEQ;
            #pragma unroll
            for (int nt = 0; nt < 8; nt++) {
                int col = wn * 64 + nt * 8 + 2 * t;
                float bb0 = bias[col], bb1 = bias[col + 1];
                Vb[(size_t)col * SEQ + s]           = __uint_as_float(f2tf(acc[mt][nt][0] + bb0));
                Vb[(size_t)(col + 1) * SEQ + s]     = __uint_as_float(f2tf(acc[mt][nt][1] + bb1));
                Vb[(size_t)col * SEQ + s + 8]       = __uint_as_float(f2tf(acc[mt][nt][2] + bb0));
                Vb[(size_t)(col + 1) * SEQ + s + 8] = __uint_as_float(f2tf(acc[mt][nt][3] + bb1));
            }
        }
    }
}

// ===========================================================================
// Flash attention, FA2-style (UNCHANGED from round 12, the measured best).
// 4 warps/block, warp owns 16 q-rows; Q in regs; P via shuffles; 1 barrier/iter.
// ===========================================================================
#define FL_SMEM (17664 * 4)

__global__ __launch_bounds__(128, 2) void flash_kernel(float* __restrict__ Out)
{
    extern __shared__ uint32_t ds[];
    uint32_t sb = smem_u32(ds);

    int b  = blockIdx.y;
    int m0 = blockIdx.x * 64;
    const float* Qg = g_q + (size_t)b * SEQ * DH + (size_t)m0 * DH;
    const float* Kg = g_k + (size_t)b * SEQ * DH;
    const float* Vt = g_v + (size_t)b * DH * SEQ;
    float*       Ob = Out + (size_t)b * SEQ * DH + (size_t)m0 * DH;

    int tid = threadIdx.x, lane = tid & 31, wq = tid >> 5;
    int g = lane >> 2, t = lane & 3;

    #pragma unroll
    for (int it = 0; it < 16; it++) {
        int idx = tid + it * 128, r = idx >> 5, c = idx & 31;
        cp16(&ds[r * 132 + c * 4], Qg + (size_t)r * DH + c * 4);
    }
    CP_COMMIT(); CP_WAIT0(); __syncthreads();

    int rA  = (lane & 7) + ((lane & 8) ? 8 : 0);
    int kwA = (lane & 16) ? 4 : 0;
    uint32_t qa = sb + (((wq * 16 + rA) * 132 + kwA) << 2);
    uint32_t q[16][4];
    #pragma unroll
    for (int ks = 0; ks < 16; ks++) ldsm4(q[ks], qa + ks * 32);
    __syncthreads();

    #pragma unroll
    for (int it = 0; it < 8; it++) {
        int idx = tid + it * 128, r = idx >> 5, c = idx & 31;
        cp16(&ds[r * 132 + c * 4], Kg + (size_t)r * DH + c * 4);
    }
    #pragma unroll
    for (int it = 0; it < 8; it++) {
        int idx = tid + it * 128, r = idx >> 3, c = idx & 7;
        cp16(&ds[8448 + r * 36 + c * 4], Vt + (size_t)r * SEQ + c * 4);
    }
    CP_COMMIT();

    int rB  = (lane & 7) + ((lane & 16) ? 8 : 0);
    int kwB = (lane & 8) ? 4 : 0;
    uint32_t kb_off = (uint32_t)(rB * 132 + kwB);
    uint32_t vb_off = (uint32_t)(rB * 36 + kwB);

    float m0r = -1e30f, m1r = -1e30f, l0 = 0.f, l1 = 0.f;
    float o[16][4];
    #pragma unroll
    for (int i = 0; i < 16; i++)
        #pragma unroll
        for (int qd = 0; qd < 4; qd++) o[i][qd] = 0.f;

    const float scaleQK = 0.08838834764831845f;
    int srcA = (lane & ~3) | (t >> 1);
    int srcB = srcA + 2;

    for (int i = 0; i < SEQ / 32; i++) {
        int cur = i & 1;
        CP_WAIT0();
        __syncthreads();

        if (i < SEQ / 32 - 1) {
            int k1 = (i + 1) * 32;
            uint32_t* Kn = ds + (cur ^ 1) * 4224;
            uint32_t* Vn = ds + 8448 + (cur ^ 1) * 4608;
            #pragma unroll
            for (int it = 0; it < 8; it++) {
                int idx = tid + it * 128, r = idx >> 5, c = idx & 31;
                cp16(&Kn[r * 132 + c * 4], Kg + (size_t)(k1 + r) * DH + c * 4);
            }
            #pragma unroll
            for (int it = 0; it < 8; it++) {
                int idx = tid + it * 128, r = idx >> 3, c = idx & 7;
                cp16(&Vn[r * 36 + c * 4], Vt + (size_t)r * SEQ + k1 + c * 4);
            }
            CP_COMMIT();
        }

        uint32_t Kb = sb + ((cur * 4224) << 2);
        uint32_t Vb = sb + ((8448 + cur * 4608) << 2);

        float s_[4][4];
        #pragma unroll
        for (int j = 0; j < 4; j++)
            #pragma unroll
            for (int qd = 0; qd < 4; qd++) s_[j][qd] = 0.f;

        #pragma unroll
        for (int ks = 0; ks < 16; ks++) {
            uint32_t B0[4], B1[4];
            ldsm4(B0, Kb + ((kb_off + ks * 8) << 2));
            ldsm4(B1, Kb + ((kb_off + 2112 + ks * 8) << 2));
            mma8(s_[0], q[ks], B0);
            mma8(s_[1], q[ks], B0 + 2);
            mma8(s_[2], q[ks], B1);
            mma8(s_[3], q[ks], B1 + 2);
        }
        #pragma unroll
        for (int j = 0; j < 4; j++)
            #pragma unroll
            for (int qd = 0; qd < 4; qd++) s_[j][qd] *= scaleQK;

        float mx0 = -1e30f, mx1 = -1e30f;
        #pragma unroll
        for (int j = 0; j < 4; j++) {
            mx0 = fmaxf(mx0, fmaxf(s_[j][0], s_[j][1]));
            mx1 = fmaxf(mx1, fmaxf(s_[j][2], s_[j][3]));
        }
        mx0 = fmaxf(mx0, __shfl_xor_sync(0xffffffffu, mx0, 1));
        mx0 = fmaxf(mx0, __shfl_xor_sync(0xffffffffu, mx0, 2));
        mx1 = fmaxf(mx1, __shfl_xor_sync(0xffffffffu, mx1, 1));
        mx1 = fmaxf(mx1, __shfl_xor_sync(0xffffffffu, mx1, 2));

        float mn0 = fmaxf(m0r, mx0), mn1 = fmaxf(m1r, mx1);
        float sc0 = __expf(m0r - mn0), sc1 = __expf(m1r - mn1);
        m0r = mn0; m1r = mn1;

        uint32_t p[4][4];
        float ts0 = 0.f, ts1 = 0.f;
        #pragma unroll
        for (int j = 0; j < 4; j++) {
            float e0 = __expf(s_[j][0] - mn0);
            float e1 = __expf(s_[j][1] - mn0);
            float e2 = __expf(s_[j][2] - mn1);
            float e3 = __expf(s_[j][3] - mn1);
            ts0 += e0 + e1; ts1 += e2 + e3;
            p[j][0] = f2tf(e0); p[j][1] = f2tf(e1);
            p[j][2] = f2tf(e2); p[j][3] = f2tf(e3);
        }
        ts0 += __shfl_xor_sync(0xffffffffu, ts0, 1);
        ts0 += __shfl_xor_sync(0xffffffffu, ts0, 2);
        ts1 += __shfl_xor_sync(0xffffffffu, ts1, 1);
        ts1 += __shfl_xor_sync(0xffffffffu, ts1, 2);
        l0 = l0 * sc0 + ts0;
        l1 = l1 * sc1 + ts1;

        #pragma unroll
        for (int nt = 0; nt < 16; nt++) {
            o[nt][0] *= sc0; o[nt][1] *= sc0;
            o[nt][2] *= sc1; o[nt][3] *= sc1;
        }

        #pragma unroll
        for (int ks = 0; ks < 4; ks++) {
            uint32_t x0 = __shfl_sync(0xffffffffu, p[ks][0], srcA);
            uint32_t x1 = __shfl_sync(0xffffffffu, p[ks][1], srcA);
            uint32_t x2 = __shfl_sync(0xffffffffu, p[ks][2], srcA);
            uint32_t x3 = __shfl_sync(0xffffffffu, p[ks][3], srcA);
            uint32_t y0 = __shfl_sync(0xffffffffu, p[ks][0], srcB);
            uint32_t y1 = __shfl_sync(0xffffffffu, p[ks][1], srcB);
            uint32_t y2 = __shfl_sync(0xffffffffu, p[ks][2], srcB);
            uint32_t y3 = __shfl_sync(0xffffffffu, p[ks][3], srcB);
            uint32_t A[4];
            A[0] = (t & 1) ? x1 : x0;
            A[1] = (t & 1) ? x3 : x2;
            A[2] = (t & 1) ? y1 : y0;
            A[3] = (t & 1) ? y3 : y2;
            #pragma unroll
            for (int p8 = 0; p8 < 8; p8++) {
                uint32_t Bv[4];
                ldsm4(Bv, Vb + ((vb_off + (uint32_t)(p8 * 16 * 36 + ks * 8)) << 2));
                mma8(o[p8 * 2],     A, Bv);
                mma8(o[p8 * 2 + 1], A, Bv + 2);
            }
        }
    }

    float i0 = 1.0f / l0, i1 = 1.0f / l1;
    int row0 = wq * 16 + g, row1 = row0 + 8;
    #pragma unroll
    for (int nt = 0; nt < 16; nt++) {
        int col = nt * 8 + 2 * t;
        float2 lo = { o[nt][0] * i0, o[nt][1] * i0 };
        float2 hi = { o[nt][2] * i1, o[nt][3] * i1 };
        *(float2*)(Ob + (size_t)row0 * DH + col) = lo;
        *(float2*)(Ob + (size_t)row1 * DH + col) = hi;
    }
}

// ===========================================================================
extern "C" void kernel_launch(void* const* d_in, const int* in_sizes, int n_in,
                              void* d_out, int out_size)
{
    const float* q_in = (const float*)d_in[0];
    const float* k_in = (const float*)d_in[1];
    const float* v_in = (const float*)d_in[2];
    const float* Wq   = (const float*)d_in[3];
    const float* Wk   = (const float*)d_in[4];
    const float* Wv   = (const float*)d_in[5];
    const float* bq   = (const float*)d_in[6];
    const float* bk   = (const float*)d_in[7];
    const float* bv   = (const float*)d_in[8];
    float* out        = (float*)d_out;

    static bool attr_done = false;
    if (!attr_done) {
        cudaFuncSetAttribute(proj_kernel,  cudaFuncAttributeMaxDynamicSharedMemorySize, PJ_SMEM);
        cudaFuncSetAttribute(flash_kernel, cudaFuncAttributeMaxDynamicSharedMemorySize, FL_SMEM);
        attr_done = true;
    }

    wprep_kernel<<<dim3(64, 3), 256>>>(Wq, Wk, Wv);
    proj_kernel<<<dim3(MTOT / 128, 3), 256, PJ_SMEM>>>(q_in, k_in, v_in, bq, bk, bv);
    flash_kernel<<<dim3(SEQ / 64, NB), 128, FL_SMEM>>>(out);
}

// round 15
// speedup vs baseline: 2.3751x; 1.3930x over previous
#include <cuda_runtime.h>
#include <cuda_fp16.h>
#include <cstdint>

#define NB 8
#define SEQ 2048
#define DIN 512
#define DH 128
#define MTOT (NB*SEQ)

// Scratch (device globals: allocation-free rule)
__device__ __half h_q[MTOT*DH];   // [b][s][dh], pre-scaled by 1/sqrt(DH)
__device__ __half h_k[MTOT*DH];   // [b][s][dh]
__device__ __half h_v[MTOT*DH];   // TRANSPOSED: [b][dh][s]
__device__ float  g_wt[3*DH*DIN]; // W tf32-rounded, transposed: [sel][n][k]

// ---------------------------------------------------------------------------
// helpers (baseline sm_75/sm_80 ISA only)
// ---------------------------------------------------------------------------
__device__ __forceinline__ uint32_t smem_u32(const void* p) {
    uint32_t a;
    asm("{ .reg .u64 t; cvta.to.shared.u64 t, %1; cvt.u32.u64 %0, t; }" : "=r"(a) : "l"(p));
    return a;
}
__device__ __forceinline__ uint32_t f2tf(float x) {
    uint32_t u;
    asm("cvt.rna.tf32.f32 %0, %1;" : "=r"(u) : "f"(x));
    return u;
}
// pack two fp32 -> fp16x2 (lo = first arg)
__device__ __forceinline__ uint32_t f2h2(float lo, float hi) {
    uint32_t r;
    asm("cvt.rn.f16x2.f32 %0, %1, %2;" : "=r"(r) : "f"(hi), "f"(lo));
    return r;
}
__device__ __forceinline__ void mma8(float* c, const uint32_t* a, const uint32_t* b) {
    asm volatile(
        "mma.sync.aligned.m16n8k8.row.col.f32.tf32.tf32.f32 "
        "{%0,%1,%2,%3}, {%4,%5,%6,%7}, {%8,%9}, {%0,%1,%2,%3};"
        : "+f"(c[0]), "+f"(c[1]), "+f"(c[2]), "+f"(c[3])
        : "r"(a[0]), "r"(a[1]), "r"(a[2]), "r"(a[3]), "r"(b[0]), "r"(b[1]));
}
__device__ __forceinline__ void mma16(float* c, const uint32_t* a, const uint32_t* b) {
    asm volatile(
        "mma.sync.aligned.m16n8k16.row.col.f32.f16.f16.f32 "
        "{%0,%1,%2,%3}, {%4,%5,%6,%7}, {%8,%9}, {%0,%1,%2,%3};"
        : "+f"(c[0]), "+f"(c[1]), "+f"(c[2]), "+f"(c[3])
        : "r"(a[0]), "r"(a[1]), "r"(a[2]), "r"(a[3]), "r"(b[0]), "r"(b[1]));
}
__device__ __forceinline__ void ldsm4(uint32_t* r, uint32_t addr) {
    asm volatile("ldmatrix.sync.aligned.m8n8.x4.shared.b16 {%0,%1,%2,%3}, [%4];"
        : "=r"(r[0]), "=r"(r[1]), "=r"(r[2]), "=r"(r[3]) : "r"(addr));
}
__device__ __forceinline__ void cp16(void* dst, const void* src) {
    uint32_t d;
    asm("{ .reg .u64 t; cvta.to.shared.u64 t, %1; cvt.u32.u64 %0, t; }" : "=r"(d) : "l"(dst));
    asm volatile("cp.async.cg.shared.global [%0], [%1], 16;" :: "r"(d), "l"(src));
}
#define CP_COMMIT() asm volatile("cp.async.commit_group;" ::: "memory")
#define CP_WAIT1()  asm volatile("cp.async.wait_group 1;" ::: "memory")
#define CP_WAIT0()  asm volatile("cp.async.wait_group 0;" ::: "memory")

// ===========================================================================
// wprep: round W to tf32 and transpose into g_wt[sel][n][k].
// ===========================================================================
__global__ __launch_bounds__(256) void wprep_kernel(
    const float* __restrict__ w0, const float* __restrict__ w1, const float* __restrict__ w2)
{
    int sel = blockIdx.y;
    const float* W  = sel == 0 ? w0 : (sel == 1 ? w1 : w2);
    float*       Wt = g_wt + (size_t)sel * DH * DIN;
    int idx = blockIdx.x * 256 + threadIdx.x;
    int k = idx >> 5, n4 = (idx & 31) * 4;
    float4 v = *(const float4*)(W + (size_t)k * DH + n4);
    Wt[(size_t)(n4 + 0) * DIN + k] = __uint_as_float(f2tf(v.x));
    Wt[(size_t)(n4 + 1) * DIN + k] = __uint_as_float(f2tf(v.y));
    Wt[(size_t)(n4 + 2) * DIN + k] = __uint_as_float(f2tf(v.z));
    Wt[(size_t)(n4 + 3) * DIN + k] = __uint_as_float(f2tf(v.w));
}

// ===========================================================================
// proj (tf32 engine unchanged from round 13); epilogue emits fp16.
// q pre-scaled by 1/sqrt(DH).  V written TRANSPOSED fp16 [b][dh][s].
// ===========================================================================
#define PJ_SMEM (18432 * 4)

__global__ __launch_bounds__(256, 2) void proj_kernel(
    const float* __restrict__ x0, const float* __restrict__ x1, const float* __restrict__ x2,
    const float* __restrict__ b0, const float* __restrict__ b1, const float* __restrict__ b2)
{
    extern __shared__ uint32_t ds[];
    uint32_t sb = smem_u32(ds);

    int sel = blockIdx.y;
    const float* X    = sel == 0 ? x0 : (sel == 1 ? x1 : x2);
    const float* bias = sel == 0 ? b0 : (sel == 1 ? b1 : b2);
    const float* Wt   = g_wt + (size_t)sel * DH * DIN;

    int m0  = blockIdx.x * 128;
    int tid = threadIdx.x;
    int lane = tid & 31, wid = tid >> 5;
    int wm = wid & 3, wn = wid >> 2;
    int g = lane >> 2, t = lane & 3;

    int rA  = (lane & 7) + ((lane & 8) ? 8 : 0);
    int kwA = (lane & 16) ? 4 : 0;
    int rB  = (lane & 7) + ((lane & 16) ? 8 : 0);
    int kwB = (lane & 8) ? 4 : 0;

    float acc[2][8][4];
    #pragma unroll
    for (int i = 0; i < 2; i++)
        #pragma unroll
        for (int j = 0; j < 8; j++)
            #pragma unroll
            for (int q = 0; q < 4; q++) acc[i][j][q] = 0.f;

    #pragma unroll
    for (int it = 0; it < 4; it++) {
        int idx = tid + it * 256, r = idx >> 3, c = idx & 7;
        cp16(&ds[r * 36 + c * 4],        X  + (size_t)(m0 + r) * DIN + c * 4);
        cp16(&ds[9216 + r * 36 + c * 4], Wt + (size_t)r * DIN + c * 4);
    }
    CP_COMMIT();

    for (int i = 0; i < 16; i++) {
        int cur = i & 1;
        if (i < 15) {
            int k1 = (i + 1) * 32;
            uint32_t* Xn = ds + (cur ^ 1) * 4608;
            uint32_t* Wn = ds + 9216 + (cur ^ 1) * 4608;
            #pragma unroll
            for (int it = 0; it < 4; it++) {
                int idx = tid + it * 256, r = idx >> 3, c = idx & 7;
                cp16(&Xn[r * 36 + c * 4], X  + (size_t)(m0 + r) * DIN + k1 + c * 4);
                cp16(&Wn[r * 36 + c * 4], Wt + (size_t)r * DIN + k1 + c * 4);
            }
            CP_COMMIT();
            CP_WAIT1();
        } else {
            CP_WAIT0();
        }
        __syncthreads();

        uint32_t Xb = sb + ((cur * 4608) << 2);
        uint32_t Wb = sb + ((9216 + cur * 4608) << 2);

        uint32_t af[2][4][4];
        #pragma unroll
        for (int mt = 0; mt < 2; mt++)
            #pragma unroll
            for (int ks = 0; ks < 4; ks++) {
                ldsm4(af[mt][ks], Xb + (((wm * 32 + mt * 16 + rA) * 36 + ks * 8 + kwA) << 2));
                #pragma unroll
                for (int j = 0; j < 4; j++)
                    af[mt][ks][j] = f2tf(__uint_as_float(af[mt][ks][j]));
            }
        #pragma unroll
        for (int ks = 0; ks < 4; ks++) {
            uint32_t bf[4][4];
            #pragma unroll
            for (int p = 0; p < 4; p++)
                ldsm4(bf[p], Wb + (((wn * 64 + p * 16 + rB) * 36 + ks * 8 + kwB) << 2));
            #pragma unroll
            for (int mt = 0; mt < 2; mt++)
                #pragma unroll
                for (int nt = 0; nt < 8; nt++)
                    mma8(acc[mt][nt], af[mt][ks], &bf[nt >> 1][(nt & 1) * 2]);
        }
        __syncthreads();
    }

    const float qscale = 0.08838834764831845f;  // 1/sqrt(128), folded into q
    #pragma unroll
    for (int mt = 0; mt < 2; mt++) {
        int m = m0 + wm * 32 + mt * 16 + g;
        if (sel != 2) {
            __half* Out = sel == 0 ? h_q : h_k;
            float sc = sel == 0 ? qscale : 1.0f;
            #pragma unroll
            for (int nt = 0; nt < 8; nt++) {
                int col = wn * 64 + nt * 8 + 2 * t;
                float bb0 = bias[col], bb1 = bias[col + 1];
                uint32_t lo = f2h2((acc[mt][nt][0] + bb0) * sc, (acc[mt][nt][1] + bb1) * sc);
                uint32_t hi = f2h2((acc[mt][nt][2] + bb0) * sc, (acc[mt][nt][3] + bb1) * sc);
                *(uint32_t*)(Out + (size_t)m * DH + col)       = lo;
                *(uint32_t*)(Out + (size_t)(m + 8) * DH + col) = hi;
            }
        } else {
            int b = m >> 11, s = m & 2047;
            __half* Vb = h_v + (size_t)b * DH * SEQ;
            #pragma unroll
            for (int nt = 0; nt < 8; nt++) {
                int col = wn * 64 + nt * 8 + 2 * t;
                float bb0 = bias[col], bb1 = bias[col + 1];
                Vb[(size_t)col * SEQ + s]           = __float2half_rn(acc[mt][nt][0] + bb0);
                Vb[(size_t)(col + 1) * SEQ + s]     = __float2half_rn(acc[mt][nt][1] + bb1);
                Vb[(size_t)col * SEQ + s + 8]       = __float2half_rn(acc[mt][nt][2] + bb0);
                Vb[(size_t)(col + 1) * SEQ + s + 8] = __float2half_rn(acc[mt][nt][3] + bb1);
            }
        }
    }
}

// ===========================================================================
// Flash attention, fp16 (m16n8k16).  4 warps/block, warp owns 16 q-rows.
// BM=64, TN=32.  Q in regs (32), P->A relayout is per-lane packing (no shfl).
// Smem (u32 words): K0 @0 (32x68=2176), K1 @2176,
//                   V0 @4352 (128x20=2560), V1 @6912.  Total 9472 w = 37.9 KB.
// Q staged once at [0, 4352) before K loads.
// ===========================================================================
#define FL_SMEM (9472 * 4)

__global__ __launch_bounds__(128, 3) void flash_kernel(float* __restrict__ Out)
{
    extern __shared__ uint32_t ds[];
    uint32_t sb = smem_u32(ds);

    int b  = blockIdx.y;
    int m0 = blockIdx.x * 64;
    const __half* Qg = h_q + (size_t)b * SEQ * DH + (size_t)m0 * DH;
    const __half* Kg = h_k + (size_t)b * SEQ * DH;
    const __half* Vt = h_v + (size_t)b * DH * SEQ;
    float*        Ob = Out + (size_t)b * SEQ * DH + (size_t)m0 * DH;

    int tid = threadIdx.x, lane = tid & 31, wq = tid >> 5;
    int g = lane >> 2, t = lane & 3;

    // ---- stage Q (64 rows x 128 fp16, stride 68 words), lift to regs ----
    #pragma unroll
    for (int it = 0; it < 8; it++) {
        int idx = tid + it * 128, r = idx >> 4, c = idx & 15;
        cp16(&ds[r * 68 + c * 4], Qg + (size_t)r * DH + c * 8);
    }
    CP_COMMIT(); CP_WAIT0(); __syncthreads();

    int rA  = (lane & 7) + ((lane & 8) ? 8 : 0);
    int kwA = (lane & 16) ? 4 : 0;
    uint32_t qa = sb + (((wq * 16 + rA) * 68 + kwA) << 2);
    uint32_t q[8][4];
    #pragma unroll
    for (int ks = 0; ks < 8; ks++) ldsm4(q[ks], qa + ks * 32);
    __syncthreads();   // staging free before K overwrites it

    // ---- K0 / V0 ----
    #pragma unroll
    for (int it = 0; it < 4; it++) {
        int idx = tid + it * 128, r = idx >> 4, c = idx & 15;
        cp16(&ds[r * 68 + c * 4], Kg + (size_t)r * DH + c * 8);
    }
    #pragma unroll
    for (int it = 0; it < 4; it++) {
        int idx = tid + it * 128, r = idx >> 2, c = idx & 3;
        cp16(&ds[4352 + r * 20 + c * 4], Vt + (size_t)r * SEQ + c * 8);
    }
    CP_COMMIT();

    int rB  = (lane & 7) + ((lane & 16) ? 8 : 0);
    int kwB = (lane & 8) ? 4 : 0;
    uint32_t kb_off = (uint32_t)(rB * 68 + kwB);
    uint32_t vb_off = (uint32_t)(rB * 20 + kwB);

    float m0r = -1e30f, m1r = -1e30f, l0 = 0.f, l1 = 0.f;
    float o[16][4];
    #pragma unroll
    for (int i = 0; i < 16; i++)
        #pragma unroll
        for (int qd = 0; qd < 4; qd++) o[i][qd] = 0.f;

    for (int i = 0; i < SEQ / 32; i++) {
        int cur = i & 1;
        CP_WAIT0();
        __syncthreads();   // K(i)/V(i) ready; all warps past iter i-1

        if (i < SEQ / 32 - 1) {
            int k1 = (i + 1) * 32;
            uint32_t* Kn = ds + (cur ^ 1) * 2176;
            uint32_t* Vn = ds + 4352 + (cur ^ 1) * 2560;
            #pragma unroll
            for (int it = 0; it < 4; it++) {
                int idx = tid + it * 128, r = idx >> 4, c = idx & 15;
                cp16(&Kn[r * 68 + c * 4], Kg + (size_t)(k1 + r) * DH + c * 8);
            }
            #pragma unroll
            for (int it = 0; it < 4; it++) {
                int idx = tid + it * 128, r = idx >> 2, c = idx & 3;
                cp16(&Vn[r * 20 + c * 4], Vt + (size_t)r * SEQ + k1 + c * 8);
            }
            CP_COMMIT();
        }

        uint32_t Kb = sb + ((cur * 2176) << 2);
        uint32_t Vb = sb + ((4352 + cur * 2560) << 2);

        // ---- S = Q . K^T  (q pre-scaled) ----
        float s_[4][4];
        #pragma unroll
        for (int j = 0; j < 4; j++)
            #pragma unroll
            for (int qd = 0; qd < 4; qd++) s_[j][qd] = 0.f;

        #pragma unroll
        for (int ks = 0; ks < 8; ks++) {
            uint32_t B0[4], B1[4];
            ldsm4(B0, Kb + ((kb_off + ks * 8) << 2));           // key-tiles 0,1
            ldsm4(B1, Kb + ((kb_off + 1088 + ks * 8) << 2));    // key-tiles 2,3 (16*68)
            mma16(s_[0], q[ks], B0);
            mma16(s_[1], q[ks], B0 + 2);
            mma16(s_[2], q[ks], B1);
            mma16(s_[3], q[ks], B1 + 2);
        }

        // ---- warp-local online softmax (rows g and g+8) ----
        float mx0 = -1e30f, mx1 = -1e30f;
        #pragma unroll
        for (int j = 0; j < 4; j++) {
            mx0 = fmaxf(mx0, fmaxf(s_[j][0], s_[j][1]));
            mx1 = fmaxf(mx1, fmaxf(s_[j][2], s_[j][3]));
        }
        mx0 = fmaxf(mx0, __shfl_xor_sync(0xffffffffu, mx0, 1));
        mx0 = fmaxf(mx0, __shfl_xor_sync(0xffffffffu, mx0, 2));
        mx1 = fmaxf(mx1, __shfl_xor_sync(0xffffffffu, mx1, 1));
        mx1 = fmaxf(mx1, __shfl_xor_sync(0xffffffffu, mx1, 2));

        float mn0 = fmaxf(m0r, mx0), mn1 = fmaxf(m1r, mx1);
        float sc0 = __expf(m0r - mn0), sc1 = __expf(m1r - mn1);
        m0r = mn0; m1r = mn1;

        // P = exp(s - m) packed fp16x2 directly into A-frag layout
        uint32_t pA[2][4];
        float ts0 = 0.f, ts1 = 0.f;
        #pragma unroll
        for (int j = 0; j < 4; j++) {
            float e0 = __expf(s_[j][0] - mn0);
            float e1 = __expf(s_[j][1] - mn0);
            float e2 = __expf(s_[j][2] - mn1);
            float e3 = __expf(s_[j][3] - mn1);
            ts0 += e0 + e1; ts1 += e2 + e3;
            pA[j >> 1][(j & 1) * 2 + 0] = f2h2(e0, e1);   // row g
            pA[j >> 1][(j & 1) * 2 + 1] = f2h2(e2, e3);   // row g+8
        }
        ts0 += __shfl_xor_sync(0xffffffffu, ts0, 1);
        ts0 += __shfl_xor_sync(0xffffffffu, ts0, 2);
        ts1 += __shfl_xor_sync(0xffffffffu, ts1, 1);
        ts1 += __shfl_xor_sync(0xffffffffu, ts1, 2);
        l0 = l0 * sc0 + ts0;
        l1 = l1 * sc1 + ts1;

        // ---- rescale O ----
        #pragma unroll
        for (int nt = 0; nt < 16; nt++) {
            o[nt][0] *= sc0; o[nt][1] *= sc0;
            o[nt][2] *= sc1; o[nt][3] *= sc1;
        }

        // ---- O += P . V  (2 k16-steps over the 32 keys) ----
        #pragma unroll
        for (int ks2 = 0; ks2 < 2; ks2++) {
            #pragma unroll
            for (int p8 = 0; p8 < 8; p8++) {
                uint32_t Bv[4];
                ldsm4(Bv, Vb + ((vb_off + (uint32_t)(p8 * 320 + ks2 * 8)) << 2));
                mma16(o[p8 * 2],     pA[ks2], Bv);
                mma16(o[p8 * 2 + 1], pA[ks2], Bv + 2);
            }
        }
    }

    // ---- epilogue: O / l ----
    float i0 = 1.0f / l0, i1 = 1.0f / l1;
    int row0 = wq * 16 + g, row1 = row0 + 8;
    #pragma unroll
    for (int nt = 0; nt < 16; nt++) {
        int col = nt * 8 + 2 * t;
        float2 lo = { o[nt][0] * i0, o[nt][1] * i0 };
        float2 hi = { o[nt][2] * i1, o[nt][3] * i1 };
        *(float2*)(Ob + (size_t)row0 * DH + col) = lo;
        *(float2*)(Ob + (size_t)row1 * DH + col) = hi;
    }
}

// ===========================================================================
extern "C" void kernel_launch(void* const* d_in, const int* in_sizes, int n_in,
                              void* d_out, int out_size)
{
    const float* q_in = (const float*)d_in[0];
    const float* k_in = (const float*)d_in[1];
    const float* v_in = (const float*)d_in[2];
    const float* Wq   = (const float*)d_in[3];
    const float* Wk   = (const float*)d_in[4];
    const float* Wv   = (const float*)d_in[5];
    const float* bq   = (const float*)d_in[6];
    const float* bk   = (const float*)d_in[7];
    const float* bv   = (const float*)d_in[8];
    float* out        = (float*)d_out;

    static bool attr_done = false;
    if (!attr_done) {
        cudaFuncSetAttribute(proj_kernel,  cudaFuncAttributeMaxDynamicSharedMemorySize, PJ_SMEM);
        cudaFuncSetAttribute(flash_kernel, cudaFuncAttributeMaxDynamicSharedMemorySize, FL_SMEM);
        attr_done = true;
    }

    wprep_kernel<<<dim3(64, 3), 256>>>(Wq, Wk, Wv);
    proj_kernel<<<dim3(MTOT / 128, 3), 256, PJ_SMEM>>>(q_in, k_in, v_in, bq, bk, bv);
    flash_kernel<<<dim3(SEQ / 64, NB), 128, FL_SMEM>>>(out);
}